// round 2
// baseline (speedup 1.0000x reference)
#include <cuda_runtime.h>

#define B_   8
#define H_   1024
#define T_   4096
#define DC_  512
#define K_   8192
#define BT_  (B_ * T_)

// Scratch (static __device__ arrays per allocation rules)
__device__ float g_h[(size_t)BT_ * DC_];   // encoded tokens [BT, DC]  (64 MB)
__device__ float g_en[K_];                 // ||e_k||^2
__device__ int   g_ind[BT_];               // argmax code index per token

// ---------------------------------------------------------------------------
// Kernel 0: codebook squared norms. One warp per code.
// ---------------------------------------------------------------------------
__global__ void en_kernel(const float* __restrict__ embed) {
    int k    = blockIdx.x * 8 + (threadIdx.x >> 5);
    int lane = threadIdx.x & 31;
    const float* e = embed + (size_t)k * DC_;
    float s = 0.f;
    #pragma unroll
    for (int d = lane; d < DC_; d += 32) { float v = e[d]; s += v * v; }
    #pragma unroll
    for (int off = 16; off; off >>= 1) s += __shfl_xor_sync(0xFFFFFFFFu, s, off);
    if (lane == 0) g_en[k] = s;
}

// ---------------------------------------------------------------------------
// Kernel 1: encode GEMM.  h[m, n] = sum_k x[b, k, t] * W_in[n, k] + b_in[n]
//   m = b*T + t (64-token tiles never straddle b since 64 | 4096)
//   64x64 tile, Ktile=16, 256 threads, 4x4 per thread.
//   n mapped to tx -> coalesced h writes (h row-major over DC).
// ---------------------------------------------------------------------------
__global__ void encode_kernel(const float* __restrict__ x,
                              const float* __restrict__ W_in,
                              const float* __restrict__ b_in) {
    __shared__ float As[16][64];
    __shared__ float Bs[16][64];
    int tid = threadIdx.x;
    int tx = tid & 15, ty = tid >> 4;
    int m0 = blockIdx.x * 64;
    int n0 = blockIdx.y * 64;
    int b  = m0 / T_;
    int t0 = m0 % T_;
    const float* xb = x + (size_t)b * H_ * T_ + t0;

    float c[4][4];
    #pragma unroll
    for (int i = 0; i < 4; i++)
        #pragma unroll
        for (int j = 0; j < 4; j++) c[i][j] = 0.f;

    for (int k0 = 0; k0 < H_; k0 += 16) {
        // A tile: x[b, k0+kk, t0+mm] -- contiguous along mm (t) => coalesced
        #pragma unroll
        for (int r = 0; r < 4; r++) {
            int i = tid + r * 256;
            int kk = i >> 6, mm = i & 63;
            As[kk][mm] = xb[(size_t)(k0 + kk) * T_ + mm];
        }
        // B tile: W_in[n0+nn, k0+kk] -- contiguous along kk
        #pragma unroll
        for (int r = 0; r < 4; r++) {
            int i = tid + r * 256;
            int nn = i >> 4, kk = i & 15;
            Bs[kk][nn] = W_in[(size_t)(n0 + nn) * H_ + k0 + kk];
        }
        __syncthreads();
        #pragma unroll
        for (int kk = 0; kk < 16; kk++) {
            float a[4], bv[4];
            #pragma unroll
            for (int i = 0; i < 4; i++) a[i]  = As[kk][ty + 16 * i];
            #pragma unroll
            for (int j = 0; j < 4; j++) bv[j] = Bs[kk][tx + 16 * j];
            #pragma unroll
            for (int i = 0; i < 4; i++)
                #pragma unroll
                for (int j = 0; j < 4; j++) c[i][j] += a[i] * bv[j];
        }
        __syncthreads();
    }

    #pragma unroll
    for (int j = 0; j < 4; j++) {
        int n = n0 + tx + 16 * j;
        float bb = b_in[n];
        #pragma unroll
        for (int i = 0; i < 4; i++)
            g_h[(size_t)(m0 + ty + 16 * i) * DC_ + n] = c[i][j] + bb;
    }
}

// ---------------------------------------------------------------------------
// Kernel 2: fused score GEMM + argmax.
//   score[m, k] = 2 * h[m]·e[k] - ||e_k||^2 ; ind[m] = argmax_k (first max).
//   One CTA per 64 tokens; loops codes in 64-chunks; never materializes scores.
//   After each chunk: per-thread best over its 4 cols, butterfly-shfl over the
//   16 lanes sharing a token (tie -> smaller index), merge into running best.
// ---------------------------------------------------------------------------
__global__ void argmax_kernel(const float* __restrict__ embed) {
    __shared__ float As[16][64];
    __shared__ float Bs[16][64];
    int tid = threadIdx.x;
    int tx = tid & 15, ty = tid >> 4;
    int m0 = blockIdx.x * 64;

    float best[4];
    int   bidx[4];
    #pragma unroll
    for (int i = 0; i < 4; i++) { best[i] = -3.4e38f; bidx[i] = 0x7fffffff; }

    for (int kc = 0; kc < K_; kc += 64) {
        float c[4][4];
        #pragma unroll
        for (int i = 0; i < 4; i++)
            #pragma unroll
            for (int j = 0; j < 4; j++) c[i][j] = 0.f;

        for (int d0 = 0; d0 < DC_; d0 += 16) {
            #pragma unroll
            for (int r = 0; r < 4; r++) {
                int i = tid + r * 256;
                int mm = i >> 4, kk = i & 15;
                As[kk][mm] = g_h[(size_t)(m0 + mm) * DC_ + d0 + kk];
            }
            #pragma unroll
            for (int r = 0; r < 4; r++) {
                int i = tid + r * 256;
                int nn = i >> 4, kk = i & 15;
                Bs[kk][nn] = embed[(size_t)(kc + nn) * DC_ + d0 + kk];
            }
            __syncthreads();
            #pragma unroll
            for (int kk = 0; kk < 16; kk++) {
                float a[4], bv[4];
                #pragma unroll
                for (int i = 0; i < 4; i++) a[i]  = As[kk][ty + 16 * i];
                #pragma unroll
                for (int j = 0; j < 4; j++) bv[j] = Bs[kk][tx + 16 * j];
                #pragma unroll
                for (int i = 0; i < 4; i++)
                    #pragma unroll
                    for (int j = 0; j < 4; j++) c[i][j] += a[i] * bv[j];
            }
            __syncthreads();
        }

        #pragma unroll
        for (int i = 0; i < 4; i++) {
            float sv = -3.4e38f;
            int   iv = 0x7fffffff;
            #pragma unroll
            for (int j = 0; j < 4; j++) {
                int n = kc + tx + 16 * j;
                float s = 2.f * c[i][j] - g_en[n];
                if (s > sv || (s == sv && n < iv)) { sv = s; iv = n; }
            }
            // butterfly over the 16 lanes that share this token
            #pragma unroll
            for (int off = 8; off; off >>= 1) {
                float so = __shfl_xor_sync(0xFFFFFFFFu, sv, off);
                int   io = __shfl_xor_sync(0xFFFFFFFFu, iv, off);
                if (so > sv || (so == sv && io < iv)) { sv = so; iv = io; }
            }
            if (sv > best[i] || (sv == best[i] && iv < bidx[i])) {
                best[i] = sv; bidx[i] = iv;
            }
        }
    }

    if (tx == 0) {
        #pragma unroll
        for (int i = 0; i < 4; i++) g_ind[m0 + ty + 16 * i] = bidx[i];
    }
}

// ---------------------------------------------------------------------------
// Kernel 3: decode GEMM with codebook gather + transposed write.
//   out[b, n, t] = sum_d embed[ind[m], d] * W_out[n, d] + b_out[n]
//   m (token) mapped to tx -> consecutive lanes write consecutive t: coalesced.
// ---------------------------------------------------------------------------
__global__ void decode_kernel(const float* __restrict__ embed,
                              const float* __restrict__ W_out,
                              const float* __restrict__ b_out,
                              float* __restrict__ out) {
    __shared__ float As[16][64];
    __shared__ float Bs[16][64];
    __shared__ int   sind[64];
    int tid = threadIdx.x;
    int tx = tid & 15, ty = tid >> 4;
    int m0 = blockIdx.x * 64;
    int n0 = blockIdx.y * 64;
    int b  = m0 / T_;
    int t0 = m0 % T_;

    if (tid < 64) sind[tid] = g_ind[m0 + tid];
    __syncthreads();

    float c[4][4];
    #pragma unroll
    for (int i = 0; i < 4; i++)
        #pragma unroll
        for (int j = 0; j < 4; j++) c[i][j] = 0.f;

    for (int d0 = 0; d0 < DC_; d0 += 16) {
        #pragma unroll
        for (int r = 0; r < 4; r++) {
            int i = tid + r * 256;
            int mm = i >> 4, kk = i & 15;
            As[kk][mm] = embed[(size_t)sind[mm] * DC_ + d0 + kk];
        }
        #pragma unroll
        for (int r = 0; r < 4; r++) {
            int i = tid + r * 256;
            int nn = i >> 4, kk = i & 15;
            Bs[kk][nn] = W_out[(size_t)(n0 + nn) * DC_ + d0 + kk];
        }
        __syncthreads();
        #pragma unroll
        for (int kk = 0; kk < 16; kk++) {
            float a[4], bv[4];
            #pragma unroll
            for (int i = 0; i < 4; i++) a[i]  = As[kk][tx + 16 * i];   // m on tx
            #pragma unroll
            for (int j = 0; j < 4; j++) bv[j] = Bs[kk][ty + 16 * j];   // n on ty
            #pragma unroll
            for (int i = 0; i < 4; i++)
                #pragma unroll
                for (int j = 0; j < 4; j++) c[i][j] += a[i] * bv[j];
        }
        __syncthreads();
    }

    float* ob = out + (size_t)b * H_ * T_ + t0;
    #pragma unroll
    for (int j = 0; j < 4; j++) {
        int n = n0 + ty + 16 * j;
        float bb = b_out[n];
        #pragma unroll
        for (int i = 0; i < 4; i++)
            ob[(size_t)n * T_ + tx + 16 * i] = c[i][j] + bb;
    }
}

// ---------------------------------------------------------------------------
extern "C" void kernel_launch(void* const* d_in, const int* in_sizes, int n_in,
                              void* d_out, int out_size) {
    const float* x     = (const float*)d_in[0];
    const float* embed = (const float*)d_in[1];
    const float* W_in  = (const float*)d_in[2];
    const float* b_in  = (const float*)d_in[3];
    const float* W_out = (const float*)d_in[4];
    const float* b_out = (const float*)d_in[5];
    float* out = (float*)d_out;

    en_kernel<<<K_ / 8, 256>>>(embed);
    encode_kernel<<<dim3(BT_ / 64, DC_ / 64), 256>>>(x, W_in, b_in);
    argmax_kernel<<<BT_ / 64, 256>>>(embed);
    decode_kernel<<<dim3(BT_ / 64, H_ / 64), 256>>>(embed, W_out, b_out, out);
}

// round 3
// speedup vs baseline: 2.6045x; 2.6045x over previous
#include <cuda_runtime.h>

#define B_   8
#define H_   1024
#define T_   4096
#define DC_  512
#define K_   8192
#define BT_  (B_ * T_)

#define BM 128
#define BN 128
#define BK 8

// Scratch (static __device__ arrays per allocation rules)
__device__ float g_h[(size_t)BT_ * DC_];   // encoded tokens [BT, DC]
__device__ float g_en[K_];                 // ||e_k||^2
__device__ int   g_ind[BT_];               // argmax code index per token

// ---------------------------------------------------------------------------
// Kernel 0: codebook squared norms. One warp per code.
// ---------------------------------------------------------------------------
__global__ void en_kernel(const float* __restrict__ embed) {
    int k    = blockIdx.x * 8 + (threadIdx.x >> 5);
    int lane = threadIdx.x & 31;
    const float* e = embed + (size_t)k * DC_;
    float s = 0.f;
    #pragma unroll
    for (int d = lane; d < DC_; d += 32) { float v = e[d]; s += v * v; }
    #pragma unroll
    for (int off = 16; off; off >>= 1) s += __shfl_xor_sync(0xFFFFFFFFu, s, off);
    if (lane == 0) g_en[k] = s;
}

// ---------------------------------------------------------------------------
// Shared compute macro: 8 k-steps, 8x8 per thread, vectorized LDS.
// AIDX / BIDX select which thread coordinate indexes the A / B fragment.
// ---------------------------------------------------------------------------
#define COMPUTE_TILE(AIDX, BIDX)                                              \
    _Pragma("unroll")                                                         \
    for (int kk = 0; kk < BK; kk++) {                                         \
        float4 a0 = *(float4*)&As[kk][(AIDX) * 8];                            \
        float4 a1 = *(float4*)&As[kk][(AIDX) * 8 + 4];                        \
        float4 q0 = *(float4*)&Bs[kk][(BIDX) * 8];                            \
        float4 q1 = *(float4*)&Bs[kk][(BIDX) * 8 + 4];                        \
        float av[8] = {a0.x,a0.y,a0.z,a0.w,a1.x,a1.y,a1.z,a1.w};              \
        float bw[8] = {q0.x,q0.y,q0.z,q0.w,q1.x,q1.y,q1.z,q1.w};              \
        _Pragma("unroll")                                                     \
        for (int i = 0; i < 8; i++)                                           \
            _Pragma("unroll")                                                 \
            for (int j = 0; j < 8; j++) c[i][j] += av[i] * bw[j];             \
    }

// ---------------------------------------------------------------------------
// Kernel 1: encode GEMM. h[m, n] = sum_k x[b, k, t] * W_in[n, k] + b_in[n]
//   A = x (contiguous along m=t), B = W_in (contiguous along k).
// ---------------------------------------------------------------------------
__global__ __launch_bounds__(256, 2)
void encode_kernel(const float* __restrict__ x,
                   const float* __restrict__ W_in,
                   const float* __restrict__ b_in) {
    __shared__ float As[BK][BM];
    __shared__ float Bs[BK][BN];
    int tid = threadIdx.x;
    int tx = tid & 15, ty = tid >> 4;
    int m0 = blockIdx.x * BM;
    int n0 = blockIdx.y * BN;
    int b  = m0 / T_;
    int t0 = m0 % T_;
    const float* xb = x + (size_t)b * H_ * T_ + t0;

    // A loader (m contiguous): one float4 along mm per thread
    int a_kk = tid >> 5, a_mm = (tid & 31) * 4;
    // B loader (k contiguous): one float4 along kk per thread
    int b_rr = tid >> 1, b_k4 = (tid & 1) * 4;

    float c[8][8];
    #pragma unroll
    for (int i = 0; i < 8; i++)
        #pragma unroll
        for (int j = 0; j < 8; j++) c[i][j] = 0.f;

    float4 ra = *(const float4*)&xb[(size_t)a_kk * T_ + a_mm];
    float4 rb = *(const float4*)&W_in[(size_t)(n0 + b_rr) * H_ + b_k4];

    for (int k0 = 0; k0 < H_; k0 += BK) {
        *(float4*)&As[a_kk][a_mm] = ra;
        Bs[b_k4 + 0][b_rr] = rb.x;
        Bs[b_k4 + 1][b_rr] = rb.y;
        Bs[b_k4 + 2][b_rr] = rb.z;
        Bs[b_k4 + 3][b_rr] = rb.w;
        __syncthreads();
        if (k0 + BK < H_) {
            ra = *(const float4*)&xb[(size_t)(k0 + BK + a_kk) * T_ + a_mm];
            rb = *(const float4*)&W_in[(size_t)(n0 + b_rr) * H_ + k0 + BK + b_k4];
        }
        COMPUTE_TILE(ty, tx)
        __syncthreads();
    }

    float bj[8];
    #pragma unroll
    for (int j = 0; j < 8; j++) bj[j] = b_in[n0 + tx * 8 + j];
    #pragma unroll
    for (int i = 0; i < 8; i++) {
        float* row = &g_h[(size_t)(m0 + ty * 8 + i) * DC_ + n0 + tx * 8];
        *(float4*)row       = make_float4(c[i][0]+bj[0], c[i][1]+bj[1], c[i][2]+bj[2], c[i][3]+bj[3]);
        *(float4*)(row + 4) = make_float4(c[i][4]+bj[4], c[i][5]+bj[5], c[i][6]+bj[6], c[i][7]+bj[7]);
    }
}

// ---------------------------------------------------------------------------
// Kernel 2: fused score GEMM + argmax.
//   One CTA per 128 tokens; loops codes in 128-chunks; never materializes
//   the score matrix. 256 CTAs, 2 CTAs/SM -> whole grid resident in 1 wave.
// ---------------------------------------------------------------------------
__global__ __launch_bounds__(256, 2)
void argmax_kernel(const float* __restrict__ embed) {
    __shared__ float As[BK][BM];
    __shared__ float Bs[BK][BN];
    int tid = threadIdx.x;
    int tx = tid & 15, ty = tid >> 4;
    int m0 = blockIdx.x * BM;

    int rr = tid >> 1, k4 = (tid & 1) * 4;
    const float* Abase = &g_h[(size_t)(m0 + rr) * DC_ + k4];

    float best[8];
    int   bidx[8];
    #pragma unroll
    for (int i = 0; i < 8; i++) { best[i] = -3.4e38f; bidx[i] = 0; }

    for (int kc = 0; kc < K_; kc += BN) {
        float c[8][8];
        #pragma unroll
        for (int i = 0; i < 8; i++)
            #pragma unroll
            for (int j = 0; j < 8; j++) c[i][j] = 0.f;

        const float* Bbase = &embed[(size_t)(kc + rr) * DC_ + k4];
        float4 ra = *(const float4*)Abase;
        float4 rb = *(const float4*)Bbase;

        for (int d0 = 0; d0 < DC_; d0 += BK) {
            As[k4 + 0][rr] = ra.x;
            As[k4 + 1][rr] = ra.y;
            As[k4 + 2][rr] = ra.z;
            As[k4 + 3][rr] = ra.w;
            Bs[k4 + 0][rr] = rb.x;
            Bs[k4 + 1][rr] = rb.y;
            Bs[k4 + 2][rr] = rb.z;
            Bs[k4 + 3][rr] = rb.w;
            __syncthreads();
            if (d0 + BK < DC_) {
                ra = *(const float4*)(Abase + d0 + BK);
                rb = *(const float4*)(Bbase + d0 + BK);
            }
            COMPUTE_TILE(ty, tx)
            __syncthreads();
        }

        // per-chunk argmax reduction (first-max tie-break, like jnp.argmax)
        #pragma unroll
        for (int i = 0; i < 8; i++) {
            float sv = -3.4e38f;
            int   iv = 0;
            #pragma unroll
            for (int j = 0; j < 8; j++) {
                int n = kc + tx * 8 + j;
                float s = 2.f * c[i][j] - g_en[n];
                if (s > sv) { sv = s; iv = n; }   // j ascending -> first max kept
            }
            // butterfly over the 16 lanes sharing this token (tie -> smaller idx)
            #pragma unroll
            for (int off = 8; off; off >>= 1) {
                float so = __shfl_xor_sync(0xFFFFFFFFu, sv, off);
                int   io = __shfl_xor_sync(0xFFFFFFFFu, iv, off);
                if (so > sv || (so == sv && io < iv)) { sv = so; iv = io; }
            }
            if (sv > best[i] || (sv == best[i] && iv < bidx[i])) {
                best[i] = sv; bidx[i] = iv;
            }
        }
    }

    if (tx == 0) {
        #pragma unroll
        for (int i = 0; i < 8; i++) g_ind[m0 + ty * 8 + i] = bidx[i];
    }
}

// ---------------------------------------------------------------------------
// Kernel 3: decode GEMM with codebook gather + transposed coalesced write.
//   m (token/t) mapped to tx so consecutive lanes write consecutive t.
// ---------------------------------------------------------------------------
__global__ __launch_bounds__(256, 2)
void decode_kernel(const float* __restrict__ embed,
                   const float* __restrict__ W_out,
                   const float* __restrict__ b_out,
                   float* __restrict__ out) {
    __shared__ float As[BK][BM];
    __shared__ float Bs[BK][BN];
    __shared__ int   sind[BM];
    int tid = threadIdx.x;
    int tx = tid & 15, ty = tid >> 4;
    int m0 = blockIdx.x * BM;
    int n0 = blockIdx.y * BN;
    int b  = m0 / T_;
    int t0 = m0 % T_;

    if (tid < BM) sind[tid] = g_ind[m0 + tid];
    __syncthreads();

    int rr = tid >> 1, k4 = (tid & 1) * 4;
    const float* Abase = &embed[(size_t)sind[rr] * DC_ + k4];
    const float* Bbase = &W_out[(size_t)(n0 + rr) * DC_ + k4];

    float c[8][8];
    #pragma unroll
    for (int i = 0; i < 8; i++)
        #pragma unroll
        for (int j = 0; j < 8; j++) c[i][j] = 0.f;

    float4 ra = *(const float4*)Abase;
    float4 rb = *(const float4*)Bbase;

    for (int d0 = 0; d0 < DC_; d0 += BK) {
        As[k4 + 0][rr] = ra.x;
        As[k4 + 1][rr] = ra.y;
        As[k4 + 2][rr] = ra.z;
        As[k4 + 3][rr] = ra.w;
        Bs[k4 + 0][rr] = rb.x;
        Bs[k4 + 1][rr] = rb.y;
        Bs[k4 + 2][rr] = rb.z;
        Bs[k4 + 3][rr] = rb.w;
        __syncthreads();
        if (d0 + BK < DC_) {
            ra = *(const float4*)(Abase + d0 + BK);
            rb = *(const float4*)(Bbase + d0 + BK);
        }
        COMPUTE_TILE(tx, ty)   // m on tx, n on ty
        __syncthreads();
    }

    float* ob = out + (size_t)b * H_ * T_ + t0 + tx * 8;
    #pragma unroll
    for (int j = 0; j < 8; j++) {
        int   n  = n0 + ty * 8 + j;
        float bb = b_out[n];
        *(float4*)&ob[(size_t)n * T_]     = make_float4(c[0][j]+bb, c[1][j]+bb, c[2][j]+bb, c[3][j]+bb);
        *(float4*)&ob[(size_t)n * T_ + 4] = make_float4(c[4][j]+bb, c[5][j]+bb, c[6][j]+bb, c[7][j]+bb);
    }
}

// ---------------------------------------------------------------------------
extern "C" void kernel_launch(void* const* d_in, const int* in_sizes, int n_in,
                              void* d_out, int out_size) {
    const float* x     = (const float*)d_in[0];
    const float* embed = (const float*)d_in[1];
    const float* W_in  = (const float*)d_in[2];
    const float* b_in  = (const float*)d_in[3];
    const float* W_out = (const float*)d_in[4];
    const float* b_out = (const float*)d_in[5];
    float* out = (float*)d_out;

    en_kernel<<<K_ / 8, 256>>>(embed);
    encode_kernel<<<dim3(BT_ / BM, DC_ / BN), 256>>>(x, W_in, b_in);
    argmax_kernel<<<BT_ / BM, 256>>>(embed);
    decode_kernel<<<dim3(BT_ / BM, H_ / BN), 256>>>(embed, W_out, b_out, out);
}

// round 5
// speedup vs baseline: 2.7735x; 1.0649x over previous
#include <cuda_runtime.h>
#include <cuda_bf16.h>
#include <cstdint>

#define B_   8
#define H_   1024
#define T_   4096
#define DC_  512
#define K_   8192
#define BT_  (B_ * T_)

#define BM 128
#define BN 128
#define BK 8

// ---- argmax HMMA kernel tiling ----
#define MM   128              // tokens per CTA
#define NN   128              // codes per chunk
#define DKT  64               // d-columns per smem tile step
#define TILE_BYTES_ (128 * 64 * 2)   // one 128x64 bf16 tile = 16 KB
#define OFF_A    0
#define OFF_B    (3 * TILE_BYTES_)
#define SMEM_DYN (6 * TILE_BYTES_ + 1024)   // +pad for alignment

// Scratch (static __device__ arrays per allocation rules)
__device__ __nv_bfloat16 g_h0[(size_t)BT_ * DC_];
__device__ __nv_bfloat16 g_h1[(size_t)BT_ * DC_];
__device__ __nv_bfloat16 g_h2[(size_t)BT_ * DC_];
__device__ __nv_bfloat16 g_e0[(size_t)K_ * DC_];
__device__ __nv_bfloat16 g_e1[(size_t)K_ * DC_];
__device__ __nv_bfloat16 g_e2[(size_t)K_ * DC_];
__device__ float g_en[K_];
__device__ int   g_ind[BT_];

// ---------------------------------------------------------------------------
// helpers
// ---------------------------------------------------------------------------
__device__ __forceinline__ uint32_t smem_u32(const void* p) {
    uint32_t a;
    asm("{ .reg .u64 t; cvta.to.shared.u64 t, %1; cvt.u32.u64 %0, t; }"
        : "=r"(a) : "l"(p));
    return a;
}

__device__ __forceinline__ void ldsm_x4(uint32_t* r, uint32_t addr) {
    asm volatile("ldmatrix.sync.aligned.m8n8.x4.shared.b16 {%0,%1,%2,%3}, [%4];"
                 : "=r"(r[0]), "=r"(r[1]), "=r"(r[2]), "=r"(r[3]) : "r"(addr));
}
__device__ __forceinline__ void ldsm_x2(uint32_t* r, uint32_t addr) {
    asm volatile("ldmatrix.sync.aligned.m8n8.x2.shared.b16 {%0,%1}, [%2];"
                 : "=r"(r[0]), "=r"(r[1]) : "r"(addr));
}
__device__ __forceinline__ void mma16816(float* c, const uint32_t* a,
                                         const uint32_t* b) {
    asm volatile(
        "mma.sync.aligned.m16n8k16.row.col.f32.bf16.bf16.f32 "
        "{%0,%1,%2,%3}, {%4,%5,%6,%7}, {%8,%9}, {%0,%1,%2,%3};"
        : "+f"(c[0]), "+f"(c[1]), "+f"(c[2]), "+f"(c[3])
        : "r"(a[0]), "r"(a[1]), "r"(a[2]), "r"(a[3]), "r"(b[0]), "r"(b[1]));
}

__device__ __forceinline__ unsigned pack2(__nv_bfloat16 lo, __nv_bfloat16 hi) {
    return (unsigned)__bfloat16_as_ushort(lo) |
           ((unsigned)__bfloat16_as_ushort(hi) << 16);
}

__device__ __forceinline__ void split3(float v, __nv_bfloat16& a0,
                                       __nv_bfloat16& a1, __nv_bfloat16& a2) {
    a0 = __float2bfloat16_rn(v);
    float r = v - __bfloat162float(a0);
    a1 = __float2bfloat16_rn(r);
    float r2 = r - __bfloat162float(a1);
    a2 = __float2bfloat16_rn(r2);
}

// ---------------------------------------------------------------------------
// Kernel 0: split embed into bf16x3 + squared norms. One warp per code.
// ---------------------------------------------------------------------------
__global__ void esplit_kernel(const float* __restrict__ embed) {
    int k    = blockIdx.x * 8 + (threadIdx.x >> 5);
    int lane = threadIdx.x & 31;
    const float4* e = (const float4*)(embed + (size_t)k * DC_);
    float s = 0.f;
    #pragma unroll
    for (int seg = lane; seg < DC_ / 4; seg += 32) {
        float4 v = e[seg];
        s += v.x * v.x + v.y * v.y + v.z * v.z + v.w * v.w;
        __nv_bfloat16 x0, x1, x2, y0, y1, y2, z0, z1, z2, w0, w1, w2;
        split3(v.x, x0, x1, x2); split3(v.y, y0, y1, y2);
        split3(v.z, z0, z1, z2); split3(v.w, w0, w1, w2);
        size_t o = (size_t)k * DC_ + seg * 4;
        *(uint2*)&g_e0[o] = make_uint2(pack2(x0, y0), pack2(z0, w0));
        *(uint2*)&g_e1[o] = make_uint2(pack2(x1, y1), pack2(z1, w1));
        *(uint2*)&g_e2[o] = make_uint2(pack2(x2, y2), pack2(z2, w2));
    }
    #pragma unroll
    for (int off = 16; off; off >>= 1) s += __shfl_xor_sync(0xFFFFFFFFu, s, off);
    if (lane == 0) g_en[k] = s;
}

// ---------------------------------------------------------------------------
// Shared SIMT compute macro (encode/decode)
// ---------------------------------------------------------------------------
#define COMPUTE_TILE(AIDX, BIDX)                                              \
    _Pragma("unroll")                                                         \
    for (int kk = 0; kk < BK; kk++) {                                         \
        float4 a0 = *(float4*)&As[kk][(AIDX) * 8];                            \
        float4 a1 = *(float4*)&As[kk][(AIDX) * 8 + 4];                        \
        float4 q0 = *(float4*)&Bs[kk][(BIDX) * 8];                            \
        float4 q1 = *(float4*)&Bs[kk][(BIDX) * 8 + 4];                        \
        float av[8] = {a0.x,a0.y,a0.z,a0.w,a1.x,a1.y,a1.z,a1.w};              \
        float bw[8] = {q0.x,q0.y,q0.z,q0.w,q1.x,q1.y,q1.z,q1.w};              \
        _Pragma("unroll")                                                     \
        for (int i = 0; i < 8; i++)                                           \
            _Pragma("unroll")                                                 \
            for (int j = 0; j < 8; j++) c[i][j] += av[i] * bw[j];             \
    }

// ---------------------------------------------------------------------------
// Kernel 1: encode GEMM, epilogue splits h into bf16x3.
// ---------------------------------------------------------------------------
__global__ __launch_bounds__(256, 2)
void encode_kernel(const float* __restrict__ x,
                   const float* __restrict__ W_in,
                   const float* __restrict__ b_in) {
    __shared__ float As[BK][BM];
    __shared__ float Bs[BK][BN];
    int tid = threadIdx.x;
    int tx = tid & 15, ty = tid >> 4;
    int m0 = blockIdx.x * BM;
    int n0 = blockIdx.y * BN;
    int b  = m0 / T_;
    int t0 = m0 % T_;
    const float* xb = x + (size_t)b * H_ * T_ + t0;

    int a_kk = tid >> 5, a_mm = (tid & 31) * 4;
    int b_rr = tid >> 1, b_k4 = (tid & 1) * 4;

    float c[8][8];
    #pragma unroll
    for (int i = 0; i < 8; i++)
        #pragma unroll
        for (int j = 0; j < 8; j++) c[i][j] = 0.f;

    float4 ra = *(const float4*)&xb[(size_t)a_kk * T_ + a_mm];
    float4 rb = *(const float4*)&W_in[(size_t)(n0 + b_rr) * H_ + b_k4];

    for (int k0 = 0; k0 < H_; k0 += BK) {
        *(float4*)&As[a_kk][a_mm] = ra;
        Bs[b_k4 + 0][b_rr] = rb.x;
        Bs[b_k4 + 1][b_rr] = rb.y;
        Bs[b_k4 + 2][b_rr] = rb.z;
        Bs[b_k4 + 3][b_rr] = rb.w;
        __syncthreads();
        if (k0 + BK < H_) {
            ra = *(const float4*)&xb[(size_t)(k0 + BK + a_kk) * T_ + a_mm];
            rb = *(const float4*)&W_in[(size_t)(n0 + b_rr) * H_ + k0 + BK + b_k4];
        }
        COMPUTE_TILE(ty, tx)
        __syncthreads();
    }

    float bj[8];
    #pragma unroll
    for (int j = 0; j < 8; j++) bj[j] = b_in[n0 + tx * 8 + j];
    #pragma unroll
    for (int i = 0; i < 8; i++) {
        size_t row = (size_t)(m0 + ty * 8 + i) * DC_ + n0 + tx * 8;
        uint4 p0, p1, p2;
        unsigned* u0 = (unsigned*)&p0;
        unsigned* u1 = (unsigned*)&p1;
        unsigned* u2 = (unsigned*)&p2;
        #pragma unroll
        for (int jp = 0; jp < 4; jp++) {
            float va = c[i][2 * jp]     + bj[2 * jp];
            float vb = c[i][2 * jp + 1] + bj[2 * jp + 1];
            __nv_bfloat16 a0, a1, a2, q0, q1, q2;
            split3(va, a0, a1, a2);
            split3(vb, q0, q1, q2);
            u0[jp] = pack2(a0, q0);
            u1[jp] = pack2(a1, q1);
            u2[jp] = pack2(a2, q2);
        }
        *(uint4*)&g_h0[row] = p0;
        *(uint4*)&g_h1[row] = p1;
        *(uint4*)&g_h2[row] = p2;
    }
}

// ---------------------------------------------------------------------------
// Kernel 2: fused score GEMM + argmax via mma.sync bf16x3 (fp32 emulation).
//   CTA: 128 tokens x 128-code chunks. Warp grid 4x2 (warp tile 32x64).
// ---------------------------------------------------------------------------
__global__ __launch_bounds__(256, 2)
void argmax_mma_kernel() {
    extern __shared__ unsigned char smraw[];
    unsigned char* sm = (unsigned char*)(((uintptr_t)smraw + 1023) & ~(uintptr_t)1023);
    uint32_t smb = smem_u32(sm);
    __shared__ float enS[NN];
    __shared__ float MS[MM];
    __shared__ int   MI[MM];

    int tid  = threadIdx.x;
    int warp = tid >> 5, lane = tid & 31;
    int half = warp >> 2;                 // 0: codes 0-63, 1: codes 64-127
    int warpM = (warp & 3) * 32;
    int warpN = half * 64;
    int m0   = blockIdx.x * MM;

    const __nv_bfloat16* Asrc[3] = {g_h0 + (size_t)m0 * DC_,
                                    g_h1 + (size_t)m0 * DC_,
                                    g_h2 + (size_t)m0 * DC_};
    const __nv_bfloat16* Bsrc[3] = {g_e0, g_e1, g_e2};

    // ldmatrix lane address components (swizzle col16 = kchunk ^ (row & 7))
    int rA_lo = (lane & 7) + ((lane >> 3) & 1) * 8;   // A x4: row within 16
    int kA    = lane >> 4;                            // A x4: k-chunk select
    int rB_lo = lane & 7;                             // B x2: code within 8
    int kB    = (lane >> 3) & 1;                      // B x2: k-chunk select
    int swz   = lane & 7;                             // row & 7 for both

    float best[2][2];
    int   bidx[2][2];
    #pragma unroll
    for (int mt = 0; mt < 2; mt++)
        #pragma unroll
        for (int r = 0; r < 2; r++) { best[mt][r] = -3.4e38f; bidx[mt][r] = 0; }

    for (int kc = 0; kc < K_; kc += NN) {
        __syncthreads();                  // reuse smem from previous chunk
        if (tid < NN) enS[tid] = g_en[kc + tid];

        float acc[2][8][4];
        #pragma unroll
        for (int mt = 0; mt < 2; mt++)
            #pragma unroll
            for (int nt = 0; nt < 8; nt++)
                #pragma unroll
                for (int q = 0; q < 4; q++) acc[mt][nt][q] = 0.f;

        for (int d0 = 0; d0 < DC_; d0 += DKT) {
            // ---- load 6 tiles (128 x 64 bf16, XOR swizzle) ----
            #pragma unroll
            for (int ti = 0; ti < 3; ti++) {
                const __nv_bfloat16* pa = Asrc[ti] + d0;
                const __nv_bfloat16* pb = Bsrc[ti] + (size_t)kc * DC_ + d0;
                #pragma unroll
                for (int t = 0; t < 4; t++) {
                    int s = tid + t * 256;
                    int row = s >> 3, sc = s & 7;
                    unsigned off = row * 128 + sc * 16;
                    unsigned sw  = off ^ ((off >> 3) & 0x70);
                    *(uint4*)(sm + OFF_A + ti * TILE_BYTES_ + sw) =
                        *(const uint4*)(pa + (size_t)row * DC_ + sc * 8);
                    *(uint4*)(sm + OFF_B + ti * TILE_BYTES_ + sw) =
                        *(const uint4*)(pb + (size_t)row * DC_ + sc * 8);
                }
            }
            __syncthreads();

            // ---- compute: 4 k16 steps ----
            #pragma unroll
            for (int k16 = 0; k16 < 4; k16++) {
                uint32_t Af[2][3][4];
                #pragma unroll
                for (int mt = 0; mt < 2; mt++) {
                    int rowA = warpM + mt * 16 + rA_lo;
                    uint32_t col = (unsigned)((k16 * 2 + kA) ^ swz) * 16;
                    #pragma unroll
                    for (int ti = 0; ti < 3; ti++)
                        ldsm_x4(Af[mt][ti],
                                smb + OFF_A + ti * TILE_BYTES_ + rowA * 128 + col);
                }
                #pragma unroll
                for (int nt = 0; nt < 8; nt++) {
                    int rowB = warpN + nt * 8 + rB_lo;
                    uint32_t col = (unsigned)((k16 * 2 + kB) ^ swz) * 16;
                    uint32_t Bf[3][2];
                    #pragma unroll
                    for (int ti = 0; ti < 3; ti++)
                        ldsm_x2(Bf[ti],
                                smb + OFF_B + ti * TILE_BYTES_ + rowB * 128 + col);
                    #pragma unroll
                    for (int mt = 0; mt < 2; mt++) {
                        mma16816(acc[mt][nt], Af[mt][0], Bf[0]);
                        mma16816(acc[mt][nt], Af[mt][0], Bf[1]);
                        mma16816(acc[mt][nt], Af[mt][1], Bf[0]);
                        mma16816(acc[mt][nt], Af[mt][1], Bf[1]);
                        mma16816(acc[mt][nt], Af[mt][0], Bf[2]);
                        mma16816(acc[mt][nt], Af[mt][2], Bf[0]);
                    }
                }
            }
            __syncthreads();
        }

        // ---- per-chunk argmax update (ascending code order per thread) ----
        #pragma unroll
        for (int mt = 0; mt < 2; mt++)
            #pragma unroll
            for (int r = 0; r < 2; r++) {
                float bs = best[mt][r];
                int   bi = bidx[mt][r];
                #pragma unroll
                for (int nt = 0; nt < 8; nt++) {
                    #pragma unroll
                    for (int q = 0; q < 2; q++) {
                        int ncol = warpN + nt * 8 + (lane & 3) * 2 + q;
                        float s = 2.f * acc[mt][nt][r * 2 + q] - enS[ncol];
                        int code = kc + ncol;
                        if (s > bs) { bs = s; bi = code; }
                    }
                }
                best[mt][r] = bs; bidx[mt][r] = bi;
            }
    }

    // ---- reduce across the 4 lanes sharing each row ----
    #pragma unroll
    for (int mt = 0; mt < 2; mt++)
        #pragma unroll
        for (int r = 0; r < 2; r++) {
            float bs = best[mt][r];
            int   bi = bidx[mt][r];
            #pragma unroll
            for (int off = 1; off <= 2; off <<= 1) {
                float so = __shfl_xor_sync(0xFFFFFFFFu, bs, off);
                int   io = __shfl_xor_sync(0xFFFFFFFFu, bi, off);
                if (so > bs || (so == bs && io < bi)) { bs = so; bi = io; }
            }
            best[mt][r] = bs; bidx[mt][r] = bi;
        }

    // ---- merge warp halves (codes 0-63 vs 64-127), tie -> smaller index ----
    __syncthreads();
    if (half == 1 && (lane & 3) == 0) {
        #pragma unroll
        for (int mt = 0; mt < 2; mt++)
            #pragma unroll
            for (int r = 0; r < 2; r++) {
                int row = warpM + mt * 16 + r * 8 + (lane >> 2);
                MS[row] = best[mt][r];
                MI[row] = bidx[mt][r];
            }
    }
    __syncthreads();
    if (half == 0 && (lane & 3) == 0) {
        #pragma unroll
        for (int mt = 0; mt < 2; mt++)
            #pragma unroll
            for (int r = 0; r < 2; r++) {
                int row = warpM + mt * 16 + r * 8 + (lane >> 2);
                float bs = best[mt][r];
                int   bi = bidx[mt][r];
                float os = MS[row]; int oi = MI[row];
                if (os > bs || (os == bs && oi < bi)) { bs = os; bi = oi; }
                g_ind[m0 + row] = bi;
            }
    }
}

// ---------------------------------------------------------------------------
// Kernel 3: decode GEMM with codebook gather + transposed coalesced write.
// ---------------------------------------------------------------------------
__global__ __launch_bounds__(256, 2)
void decode_kernel(const float* __restrict__ embed,
                   const float* __restrict__ W_out,
                   const float* __restrict__ b_out,
                   float* __restrict__ out) {
    __shared__ float As[BK][BM];
    __shared__ float Bs[BK][BN];
    __shared__ int   sind[BM];
    int tid = threadIdx.x;
    int tx = tid & 15, ty = tid >> 4;
    int m0 = blockIdx.x * BM;
    int n0 = blockIdx.y * BN;
    int b  = m0 / T_;
    int t0 = m0 % T_;

    if (tid < BM) sind[tid] = g_ind[m0 + tid];
    __syncthreads();

    int rr = tid >> 1, k4 = (tid & 1) * 4;
    const float* Abase = &embed[(size_t)sind[rr] * DC_ + k4];
    const float* Bbase = &W_out[(size_t)(n0 + rr) * DC_ + k4];

    float c[8][8];
    #pragma unroll
    for (int i = 0; i < 8; i++)
        #pragma unroll
        for (int j = 0; j < 8; j++) c[i][j] = 0.f;

    float4 ra = *(const float4*)Abase;
    float4 rb = *(const float4*)Bbase;

    for (int d0 = 0; d0 < DC_; d0 += BK) {
        As[k4 + 0][rr] = ra.x;
        As[k4 + 1][rr] = ra.y;
        As[k4 + 2][rr] = ra.z;
        As[k4 + 3][rr] = ra.w;
        Bs[k4 + 0][rr] = rb.x;
        Bs[k4 + 1][rr] = rb.y;
        Bs[k4 + 2][rr] = rb.z;
        Bs[k4 + 3][rr] = rb.w;
        __syncthreads();
        if (d0 + BK < DC_) {
            ra = *(const float4*)(Abase + d0 + BK);
            rb = *(const float4*)(Bbase + d0 + BK);
        }
        COMPUTE_TILE(tx, ty)
        __syncthreads();
    }

    float* ob = out + (size_t)b * H_ * T_ + t0 + tx * 8;
    #pragma unroll
    for (int j = 0; j < 8; j++) {
        int   n  = n0 + ty * 8 + j;
        float bb = b_out[n];
        *(float4*)&ob[(size_t)n * T_]     = make_float4(c[0][j]+bb, c[1][j]+bb, c[2][j]+bb, c[3][j]+bb);
        *(float4*)&ob[(size_t)n * T_ + 4] = make_float4(c[4][j]+bb, c[5][j]+bb, c[6][j]+bb, c[7][j]+bb);
    }
}

// ---------------------------------------------------------------------------
extern "C" void kernel_launch(void* const* d_in, const int* in_sizes, int n_in,
                              void* d_out, int out_size) {
    const float* x     = (const float*)d_in[0];
    const float* embed = (const float*)d_in[1];
    const float* W_in  = (const float*)d_in[2];
    const float* b_in  = (const float*)d_in[3];
    const float* W_out = (const float*)d_in[4];
    const float* b_out = (const float*)d_in[5];
    float* out = (float*)d_out;

    cudaFuncSetAttribute(argmax_mma_kernel,
                         cudaFuncAttributeMaxDynamicSharedMemorySize, SMEM_DYN);

    esplit_kernel<<<K_ / 8, 256>>>(embed);
    encode_kernel<<<dim3(BT_ / BM, DC_ / BN), 256>>>(x, W_in, b_in);
    argmax_mma_kernel<<<BT_ / MM, 256, SMEM_DYN>>>();
    decode_kernel<<<dim3(BT_ / BM, H_ / BN), 256>>>(embed, W_out, b_out, out);
}

// round 6
// speedup vs baseline: 3.5573x; 1.2826x over previous
#include <cuda_runtime.h>
#include <cuda_bf16.h>
#include <cstdint>

#define B_   8
#define H_   1024
#define T_   4096
#define DC_  512
#define K_   8192
#define BT_  (B_ * T_)

#define BM 128
#define BN 128
#define BK 8

// ---- argmax HMMA kernel tiling ----
#define MM   128              // tokens per CTA
#define NN   128              // codes per chunk
#define DKT  64               // d-columns per smem tile step
#define TILE_BYTES_ (128 * 64 * 2)   // one 128x64 bf16 tile = 16 KB
#define OFF_A    0
#define OFF_B    (2 * TILE_BYTES_)
#define SMEM_DYN (4 * TILE_BYTES_ + 1024)   // +pad for alignment

#define DELTA 0.125f          // certainty margin for 2-split scores

// Scratch (static __device__ arrays per allocation rules)
__device__ __nv_bfloat16 g_h0[(size_t)BT_ * DC_];
__device__ __nv_bfloat16 g_h1[(size_t)BT_ * DC_];
__device__ __nv_bfloat16 g_h2[(size_t)BT_ * DC_];
__device__ __nv_bfloat16 g_e0[(size_t)K_ * DC_];
__device__ __nv_bfloat16 g_e1[(size_t)K_ * DC_];
__device__ float g_en[K_];
__device__ int   g_ind[BT_];
__device__ int   g_unc[BT_];
__device__ int   g_unc_cnt;

// ---------------------------------------------------------------------------
// helpers
// ---------------------------------------------------------------------------
__device__ __forceinline__ uint32_t smem_u32(const void* p) {
    uint32_t a;
    asm("{ .reg .u64 t; cvta.to.shared.u64 t, %1; cvt.u32.u64 %0, t; }"
        : "=r"(a) : "l"(p));
    return a;
}

__device__ __forceinline__ void ldsm_x4(uint32_t* r, uint32_t addr) {
    asm volatile("ldmatrix.sync.aligned.m8n8.x4.shared.b16 {%0,%1,%2,%3}, [%4];"
                 : "=r"(r[0]), "=r"(r[1]), "=r"(r[2]), "=r"(r[3]) : "r"(addr));
}
__device__ __forceinline__ void mma16816(float* c, const uint32_t* a,
                                         const uint32_t* b) {
    asm volatile(
        "mma.sync.aligned.m16n8k16.row.col.f32.bf16.bf16.f32 "
        "{%0,%1,%2,%3}, {%4,%5,%6,%7}, {%8,%9}, {%0,%1,%2,%3};"
        : "+f"(c[0]), "+f"(c[1]), "+f"(c[2]), "+f"(c[3])
        : "r"(a[0]), "r"(a[1]), "r"(a[2]), "r"(a[3]), "r"(b[0]), "r"(b[1]));
}

__device__ __forceinline__ unsigned pack2(__nv_bfloat16 lo, __nv_bfloat16 hi) {
    return (unsigned)__bfloat16_as_ushort(lo) |
           ((unsigned)__bfloat16_as_ushort(hi) << 16);
}

__device__ __forceinline__ void split3(float v, __nv_bfloat16& a0,
                                       __nv_bfloat16& a1, __nv_bfloat16& a2) {
    a0 = __float2bfloat16_rn(v);
    float r = v - __bfloat162float(a0);
    a1 = __float2bfloat16_rn(r);
    float r2 = r - __bfloat162float(a1);
    a2 = __float2bfloat16_rn(r2);
}

// ---------------------------------------------------------------------------
// Kernel 0: split embed into bf16x2 + squared norms. One warp per code.
// ---------------------------------------------------------------------------
__global__ void esplit_kernel(const float* __restrict__ embed) {
    int k    = blockIdx.x * 8 + (threadIdx.x >> 5);
    int lane = threadIdx.x & 31;
    const float4* e = (const float4*)(embed + (size_t)k * DC_);
    float s = 0.f;
    #pragma unroll
    for (int seg = lane; seg < DC_ / 4; seg += 32) {
        float4 v = e[seg];
        s += v.x * v.x + v.y * v.y + v.z * v.z + v.w * v.w;
        __nv_bfloat16 x0, x1, x2, y0, y1, y2, z0, z1, z2, w0, w1, w2;
        split3(v.x, x0, x1, x2); split3(v.y, y0, y1, y2);
        split3(v.z, z0, z1, z2); split3(v.w, w0, w1, w2);
        size_t o = (size_t)k * DC_ + seg * 4;
        *(uint2*)&g_e0[o] = make_uint2(pack2(x0, y0), pack2(z0, w0));
        *(uint2*)&g_e1[o] = make_uint2(pack2(x1, y1), pack2(z1, w1));
    }
    #pragma unroll
    for (int off = 16; off; off >>= 1) s += __shfl_xor_sync(0xFFFFFFFFu, s, off);
    if (lane == 0) g_en[k] = s;
}

__global__ void zero_cnt_kernel() { g_unc_cnt = 0; }

// ---------------------------------------------------------------------------
// Shared SIMT compute macro (encode/decode)
// ---------------------------------------------------------------------------
#define COMPUTE_TILE(AIDX, BIDX)                                              \
    _Pragma("unroll")                                                         \
    for (int kk = 0; kk < BK; kk++) {                                         \
        float4 a0 = *(float4*)&As[kk][(AIDX) * 8];                            \
        float4 a1 = *(float4*)&As[kk][(AIDX) * 8 + 4];                        \
        float4 q0 = *(float4*)&Bs[kk][(BIDX) * 8];                            \
        float4 q1 = *(float4*)&Bs[kk][(BIDX) * 8 + 4];                        \
        float av[8] = {a0.x,a0.y,a0.z,a0.w,a1.x,a1.y,a1.z,a1.w};              \
        float bw[8] = {q0.x,q0.y,q0.z,q0.w,q1.x,q1.y,q1.z,q1.w};              \
        _Pragma("unroll")                                                     \
        for (int i = 0; i < 8; i++)                                           \
            _Pragma("unroll")                                                 \
            for (int j = 0; j < 8; j++) c[i][j] += av[i] * bw[j];             \
    }

// ---------------------------------------------------------------------------
// Kernel 1: encode GEMM, epilogue splits h into bf16x3.
// ---------------------------------------------------------------------------
__global__ __launch_bounds__(256, 2)
void encode_kernel(const float* __restrict__ x,
                   const float* __restrict__ W_in,
                   const float* __restrict__ b_in) {
    __shared__ float As[BK][BM];
    __shared__ float Bs[BK][BN];
    int tid = threadIdx.x;
    int tx = tid & 15, ty = tid >> 4;
    int m0 = blockIdx.x * BM;
    int n0 = blockIdx.y * BN;
    int b  = m0 / T_;
    int t0 = m0 % T_;
    const float* xb = x + (size_t)b * H_ * T_ + t0;

    int a_kk = tid >> 5, a_mm = (tid & 31) * 4;
    int b_rr = tid >> 1, b_k4 = (tid & 1) * 4;

    float c[8][8];
    #pragma unroll
    for (int i = 0; i < 8; i++)
        #pragma unroll
        for (int j = 0; j < 8; j++) c[i][j] = 0.f;

    float4 ra = *(const float4*)&xb[(size_t)a_kk * T_ + a_mm];
    float4 rb = *(const float4*)&W_in[(size_t)(n0 + b_rr) * H_ + b_k4];

    for (int k0 = 0; k0 < H_; k0 += BK) {
        *(float4*)&As[a_kk][a_mm] = ra;
        Bs[b_k4 + 0][b_rr] = rb.x;
        Bs[b_k4 + 1][b_rr] = rb.y;
        Bs[b_k4 + 2][b_rr] = rb.z;
        Bs[b_k4 + 3][b_rr] = rb.w;
        __syncthreads();
        if (k0 + BK < H_) {
            ra = *(const float4*)&xb[(size_t)(k0 + BK + a_kk) * T_ + a_mm];
            rb = *(const float4*)&W_in[(size_t)(n0 + b_rr) * H_ + k0 + BK + b_k4];
        }
        COMPUTE_TILE(ty, tx)
        __syncthreads();
    }

    float bj[8];
    #pragma unroll
    for (int j = 0; j < 8; j++) bj[j] = b_in[n0 + tx * 8 + j];
    #pragma unroll
    for (int i = 0; i < 8; i++) {
        size_t row = (size_t)(m0 + ty * 8 + i) * DC_ + n0 + tx * 8;
        uint4 p0, p1, p2;
        unsigned* u0 = (unsigned*)&p0;
        unsigned* u1 = (unsigned*)&p1;
        unsigned* u2 = (unsigned*)&p2;
        #pragma unroll
        for (int jp = 0; jp < 4; jp++) {
            float va = c[i][2 * jp]     + bj[2 * jp];
            float vb = c[i][2 * jp + 1] + bj[2 * jp + 1];
            __nv_bfloat16 a0, a1, a2, q0, q1, q2;
            split3(va, a0, a1, a2);
            split3(vb, q0, q1, q2);
            u0[jp] = pack2(a0, q0);
            u1[jp] = pack2(a1, q1);
            u2[jp] = pack2(a2, q2);
        }
        *(uint4*)&g_h0[row] = p0;
        *(uint4*)&g_h1[row] = p1;
        *(uint4*)&g_h2[row] = p2;
    }
}

// ---------------------------------------------------------------------------
// Kernel 2: fused score GEMM + top-2 argmax via mma.sync bf16x2 (3 products).
//   CTA: 128 tokens x 128-code chunks. Warp grid 4x2 (warp tile 32x64).
//   Emits certain argmax to g_ind; tokens with top1-top2 < DELTA to g_unc.
// ---------------------------------------------------------------------------
__global__ __launch_bounds__(256, 2)
void argmax_mma_kernel() {
    extern __shared__ unsigned char smraw[];
    unsigned char* sm = (unsigned char*)(((uintptr_t)smraw + 1023) & ~(uintptr_t)1023);
    uint32_t smb = smem_u32(sm);
    __shared__ float enS[NN];
    __shared__ float MS[MM];
    __shared__ int   MI[MM];
    __shared__ float M2[MM];

    int tid  = threadIdx.x;
    int warp = tid >> 5, lane = tid & 31;
    int half = warp >> 2;                 // 0: codes 0-63, 1: codes 64-127
    int warpM = (warp & 3) * 32;
    int warpN = half * 64;
    int m0   = blockIdx.x * MM;

    const __nv_bfloat16* Asrc[2] = {g_h0 + (size_t)m0 * DC_,
                                    g_h1 + (size_t)m0 * DC_};
    const __nv_bfloat16* Bsrc[2] = {g_e0, g_e1};

    // ldmatrix lane address components (swizzle col16 = kchunk ^ (row & 7))
    int rA_lo = (lane & 7) + ((lane >> 3) & 1) * 8;   // A x4: row within 16
    int kA    = lane >> 4;                            // A x4: k-chunk select
    int rB_lo = lane & 7;                             // B x4: code within 8
    int kB    = (lane >> 3) & 1;                      // B x4: k-chunk select
    int nB    = (lane >> 4) & 1;                      // B x4: which nt of pair
    int swz   = lane & 7;

    float best[2][2], sec[2][2];
    int   bidx[2][2];
    #pragma unroll
    for (int mt = 0; mt < 2; mt++)
        #pragma unroll
        for (int r = 0; r < 2; r++) {
            best[mt][r] = -3.4e38f; sec[mt][r] = -3.4e38f; bidx[mt][r] = 0;
        }

    for (int kc = 0; kc < K_; kc += NN) {
        __syncthreads();                  // reuse smem from previous chunk
        if (tid < NN) enS[tid] = g_en[kc + tid];

        float acc[2][8][4];
        #pragma unroll
        for (int mt = 0; mt < 2; mt++)
            #pragma unroll
            for (int nt = 0; nt < 8; nt++)
                #pragma unroll
                for (int q = 0; q < 4; q++) acc[mt][nt][q] = 0.f;

        for (int d0 = 0; d0 < DC_; d0 += DKT) {
            // ---- load 4 tiles (128 x 64 bf16, XOR swizzle) ----
            #pragma unroll
            for (int ti = 0; ti < 2; ti++) {
                const __nv_bfloat16* pa = Asrc[ti] + d0;
                const __nv_bfloat16* pb = Bsrc[ti] + (size_t)kc * DC_ + d0;
                #pragma unroll
                for (int t = 0; t < 4; t++) {
                    int s = tid + t * 256;
                    int row = s >> 3, sc = s & 7;
                    unsigned off = row * 128 + sc * 16;
                    unsigned sw  = off ^ ((off >> 3) & 0x70);
                    *(uint4*)(sm + OFF_A + ti * TILE_BYTES_ + sw) =
                        *(const uint4*)(pa + (size_t)row * DC_ + sc * 8);
                    *(uint4*)(sm + OFF_B + ti * TILE_BYTES_ + sw) =
                        *(const uint4*)(pb + (size_t)row * DC_ + sc * 8);
                }
            }
            __syncthreads();

            // ---- compute: 4 k16 steps ----
            #pragma unroll
            for (int k16 = 0; k16 < 4; k16++) {
                uint32_t Af[2][2][4];
                #pragma unroll
                for (int mt = 0; mt < 2; mt++) {
                    int rowA = warpM + mt * 16 + rA_lo;
                    uint32_t col = (unsigned)((k16 * 2 + kA) ^ swz) * 16;
                    #pragma unroll
                    for (int ti = 0; ti < 2; ti++)
                        ldsm_x4(Af[mt][ti],
                                smb + OFF_A + ti * TILE_BYTES_ + rowA * 128 + col);
                }
                #pragma unroll
                for (int ntp = 0; ntp < 4; ntp++) {
                    uint32_t Bf[2][4];   // [ti][mat]: mats 0,1=nt even; 2,3=nt odd
                    int rowB = warpN + (ntp * 2 + nB) * 8 + rB_lo;
                    uint32_t col = (unsigned)((k16 * 2 + kB) ^ swz) * 16;
                    #pragma unroll
                    for (int ti = 0; ti < 2; ti++)
                        ldsm_x4(Bf[ti],
                                smb + OFF_B + ti * TILE_BYTES_ + rowB * 128 + col);
                    #pragma unroll
                    for (int mt = 0; mt < 2; mt++)
                        #pragma unroll
                        for (int h2 = 0; h2 < 2; h2++) {
                            float* a = acc[mt][ntp * 2 + h2];
                            mma16816(a, Af[mt][0], Bf[0] + h2 * 2);
                            mma16816(a, Af[mt][0], Bf[1] + h2 * 2);
                            mma16816(a, Af[mt][1], Bf[0] + h2 * 2);
                        }
                }
            }
            __syncthreads();
        }

        // ---- per-chunk top-2 update (ascending code order per thread) ----
        #pragma unroll
        for (int mt = 0; mt < 2; mt++)
            #pragma unroll
            for (int r = 0; r < 2; r++) {
                float b1 = best[mt][r], b2 = sec[mt][r];
                int   i1 = bidx[mt][r];
                #pragma unroll
                for (int nt = 0; nt < 8; nt++) {
                    #pragma unroll
                    for (int q = 0; q < 2; q++) {
                        int ncol = warpN + nt * 8 + (lane & 3) * 2 + q;
                        float s = 2.f * acc[mt][nt][r * 2 + q] - enS[ncol];
                        if (s > b1) { b2 = b1; b1 = s; i1 = kc + ncol; }
                        else if (s > b2) b2 = s;
                    }
                }
                best[mt][r] = b1; sec[mt][r] = b2; bidx[mt][r] = i1;
            }
    }

    // ---- reduce across the 4 lanes sharing each row ----
    #pragma unroll
    for (int mt = 0; mt < 2; mt++)
        #pragma unroll
        for (int r = 0; r < 2; r++) {
            float b1 = best[mt][r], b2 = sec[mt][r];
            int   i1 = bidx[mt][r];
            #pragma unroll
            for (int off = 1; off <= 2; off <<= 1) {
                float c1 = __shfl_xor_sync(0xFFFFFFFFu, b1, off);
                int   ci = __shfl_xor_sync(0xFFFFFFFFu, i1, off);
                float c2 = __shfl_xor_sync(0xFFFFFFFFu, b2, off);
                if (c1 > b1) { b2 = fmaxf(b1, c2); b1 = c1; i1 = ci; }
                else { b2 = fmaxf(b2, c1); if (c1 == b1 && ci < i1) i1 = ci; }
            }
            best[mt][r] = b1; sec[mt][r] = b2; bidx[mt][r] = i1;
        }

    // ---- merge warp halves (codes 0-63 vs 64-127) ----
    __syncthreads();
    if (half == 1 && (lane & 3) == 0) {
        #pragma unroll
        for (int mt = 0; mt < 2; mt++)
            #pragma unroll
            for (int r = 0; r < 2; r++) {
                int row = warpM + mt * 16 + r * 8 + (lane >> 2);
                MS[row] = best[mt][r];
                MI[row] = bidx[mt][r];
                M2[row] = sec[mt][r];
            }
    }
    __syncthreads();
    if (half == 0 && (lane & 3) == 0) {
        #pragma unroll
        for (int mt = 0; mt < 2; mt++)
            #pragma unroll
            for (int r = 0; r < 2; r++) {
                int row = warpM + mt * 16 + r * 8 + (lane >> 2);
                float b1 = best[mt][r], b2 = sec[mt][r];
                int   i1 = bidx[mt][r];
                float c1 = MS[row], c2 = M2[row];
                int   ci = MI[row];
                if (c1 > b1) { b2 = fmaxf(b1, c2); b1 = c1; i1 = ci; }
                else { b2 = fmaxf(b2, c1); if (c1 == b1 && ci < i1) i1 = ci; }
                g_ind[m0 + row] = i1;
                if (b1 - b2 < DELTA) {
                    int p = atomicAdd(&g_unc_cnt, 1);
                    g_unc[p] = m0 + row;
                }
            }
    }
}

// ---------------------------------------------------------------------------
// Kernel 2b: exact fp32 rescoring fallback for uncertain tokens.
//   Persistent grid; each CTA handles tokens from the uncertain list.
// ---------------------------------------------------------------------------
__global__ __launch_bounds__(256, 4)
void fallback_kernel(const float* __restrict__ embed) {
    __shared__ float hs[DC_];
    __shared__ float ws[8];
    __shared__ int   wi[8];
    int tid = threadIdx.x;
    int warp = tid >> 5, lane = tid & 31;
    int cnt = g_unc_cnt;

    for (int u = blockIdx.x; u < cnt; u += gridDim.x) {
        int tok = g_unc[u];
        __syncthreads();
        for (int d = tid; d < DC_; d += 256) {
            size_t o = (size_t)tok * DC_ + d;
            hs[d] = __bfloat162float(g_h0[o]) + __bfloat162float(g_h1[o]) +
                    __bfloat162float(g_h2[o]);
        }
        __syncthreads();

        float b1 = -3.4e38f;
        int   i1 = 0x7fffffff;
        for (int k = warp; k < K_; k += 8) {
            const float4* e = (const float4*)(embed + (size_t)k * DC_);
            float dot = 0.f;
            #pragma unroll
            for (int seg = lane; seg < DC_ / 4; seg += 32) {
                float4 v = e[seg];
                const float4 hv = *(const float4*)&hs[seg * 4];
                dot += v.x * hv.x + v.y * hv.y + v.z * hv.z + v.w * hv.w;
            }
            #pragma unroll
            for (int off = 16; off; off >>= 1)
                dot += __shfl_xor_sync(0xFFFFFFFFu, dot, off);
            float s = 2.f * dot - g_en[k];
            if (s > b1) { b1 = s; i1 = k; }   // k ascending per warp
        }
        if (lane == 0) { ws[warp] = b1; wi[warp] = i1; }
        __syncthreads();
        if (tid == 0) {
            float fb = ws[0]; int fi = wi[0];
            #pragma unroll
            for (int w = 1; w < 8; w++) {
                if (ws[w] > fb || (ws[w] == fb && wi[w] < fi)) {
                    fb = ws[w]; fi = wi[w];
                }
            }
            g_ind[tok] = fi;
        }
    }
}

// ---------------------------------------------------------------------------
// Kernel 3: decode GEMM with codebook gather + transposed coalesced write.
// ---------------------------------------------------------------------------
__global__ __launch_bounds__(256, 2)
void decode_kernel(const float* __restrict__ embed,
                   const float* __restrict__ W_out,
                   const float* __restrict__ b_out,
                   float* __restrict__ out) {
    __shared__ float As[BK][BM];
    __shared__ float Bs[BK][BN];
    __shared__ int   sind[BM];
    int tid = threadIdx.x;
    int tx = tid & 15, ty = tid >> 4;
    int m0 = blockIdx.x * BM;
    int n0 = blockIdx.y * BN;
    int b  = m0 / T_;
    int t0 = m0 % T_;

    if (tid < BM) sind[tid] = g_ind[m0 + tid];
    __syncthreads();

    int rr = tid >> 1, k4 = (tid & 1) * 4;
    const float* Abase = &embed[(size_t)sind[rr] * DC_ + k4];
    const float* Bbase = &W_out[(size_t)(n0 + rr) * DC_ + k4];

    float c[8][8];
    #pragma unroll
    for (int i = 0; i < 8; i++)
        #pragma unroll
        for (int j = 0; j < 8; j++) c[i][j] = 0.f;

    float4 ra = *(const float4*)Abase;
    float4 rb = *(const float4*)Bbase;

    for (int d0 = 0; d0 < DC_; d0 += BK) {
        As[k4 + 0][rr] = ra.x;
        As[k4 + 1][rr] = ra.y;
        As[k4 + 2][rr] = ra.z;
        As[k4 + 3][rr] = ra.w;
        Bs[k4 + 0][rr] = rb.x;
        Bs[k4 + 1][rr] = rb.y;
        Bs[k4 + 2][rr] = rb.z;
        Bs[k4 + 3][rr] = rb.w;
        __syncthreads();
        if (d0 + BK < DC_) {
            ra = *(const float4*)(Abase + d0 + BK);
            rb = *(const float4*)(Bbase + d0 + BK);
        }
        COMPUTE_TILE(tx, ty)
        __syncthreads();
    }

    float* ob = out + (size_t)b * H_ * T_ + t0 + tx * 8;
    #pragma unroll
    for (int j = 0; j < 8; j++) {
        int   n  = n0 + ty * 8 + j;
        float bb = b_out[n];
        *(float4*)&ob[(size_t)n * T_]     = make_float4(c[0][j]+bb, c[1][j]+bb, c[2][j]+bb, c[3][j]+bb);
        *(float4*)&ob[(size_t)n * T_ + 4] = make_float4(c[4][j]+bb, c[5][j]+bb, c[6][j]+bb, c[7][j]+bb);
    }
}

// ---------------------------------------------------------------------------
extern "C" void kernel_launch(void* const* d_in, const int* in_sizes, int n_in,
                              void* d_out, int out_size) {
    const float* x     = (const float*)d_in[0];
    const float* embed = (const float*)d_in[1];
    const float* W_in  = (const float*)d_in[2];
    const float* b_in  = (const float*)d_in[3];
    const float* W_out = (const float*)d_in[4];
    const float* b_out = (const float*)d_in[5];
    float* out = (float*)d_out;

    cudaFuncSetAttribute(argmax_mma_kernel,
                         cudaFuncAttributeMaxDynamicSharedMemorySize, SMEM_DYN);

    zero_cnt_kernel<<<1, 1>>>();
    esplit_kernel<<<K_ / 8, 256>>>(embed);
    encode_kernel<<<dim3(BT_ / BM, DC_ / BN), 256>>>(x, W_in, b_in);
    argmax_mma_kernel<<<BT_ / MM, 256, SMEM_DYN>>>();
    fallback_kernel<<<256, 256>>>(embed);
    decode_kernel<<<dim3(BT_ / BM, H_ / BN), 256>>>(embed, W_out, b_out, out);
}

// round 7
// speedup vs baseline: 4.5709x; 1.2849x over previous
#include <cuda_runtime.h>
#include <cuda_bf16.h>
#include <cstdint>

#define B_   8
#define H_   1024
#define T_   4096
#define DC_  512
#define K_   8192
#define BT_  (B_ * T_)

#define BM 128
#define BN 128
#define BK 8

// ---- argmax HMMA kernel tiling ----
#define MM   128                   // tokens per CTA
#define NN   128                   // codes per chunk
#define DKT  32                    // d-columns per pipeline stage
#define TILE_B   (128 * DKT * 2)   // one 128x32 bf16 tile = 8 KB
#define STAGE_B  (4 * TILE_B)      // A0,A1,B0,B1 per stage = 32 KB
#define NSTAGE   3
#define SMEM_DYN (NSTAGE * STAGE_B + 1024)
#define TOT_STEPS ((K_ / NN) * (DC_ / DKT))   // 64 * 16 = 1024

#define DELTA 0.125f               // certainty margin for 2-split scores

// Scratch (static __device__ arrays per allocation rules)
__device__ __nv_bfloat16 g_h0[(size_t)BT_ * DC_];
__device__ __nv_bfloat16 g_h1[(size_t)BT_ * DC_];
__device__ __nv_bfloat16 g_h2[(size_t)BT_ * DC_];
__device__ __nv_bfloat16 g_e0[(size_t)K_ * DC_];
__device__ __nv_bfloat16 g_e1[(size_t)K_ * DC_];
__device__ float g_en[K_];
__device__ int   g_ind[BT_];
__device__ int   g_unc[BT_];
__device__ int   g_unc_cnt;

// ---------------------------------------------------------------------------
// helpers
// ---------------------------------------------------------------------------
__device__ __forceinline__ uint32_t smem_u32(const void* p) {
    uint32_t a;
    asm("{ .reg .u64 t; cvta.to.shared.u64 t, %1; cvt.u32.u64 %0, t; }"
        : "=r"(a) : "l"(p));
    return a;
}

__device__ __forceinline__ void cp16(uint32_t smem, const void* g) {
    asm volatile("cp.async.cg.shared.global [%0], [%1], 16;"
                 :: "r"(smem), "l"(g));
}
#define CP_COMMIT() asm volatile("cp.async.commit_group;" ::: "memory")
#define CP_WAIT1()  asm volatile("cp.async.wait_group 1;" ::: "memory")

__device__ __forceinline__ void ldsm_x4(uint32_t* r, uint32_t addr) {
    asm volatile("ldmatrix.sync.aligned.m8n8.x4.shared.b16 {%0,%1,%2,%3}, [%4];"
                 : "=r"(r[0]), "=r"(r[1]), "=r"(r[2]), "=r"(r[3]) : "r"(addr));
}
__device__ __forceinline__ void mma16816(float* c, const uint32_t* a,
                                         const uint32_t* b) {
    asm volatile(
        "mma.sync.aligned.m16n8k16.row.col.f32.bf16.bf16.f32 "
        "{%0,%1,%2,%3}, {%4,%5,%6,%7}, {%8,%9}, {%0,%1,%2,%3};"
        : "+f"(c[0]), "+f"(c[1]), "+f"(c[2]), "+f"(c[3])
        : "r"(a[0]), "r"(a[1]), "r"(a[2]), "r"(a[3]), "r"(b[0]), "r"(b[1]));
}

__device__ __forceinline__ unsigned pack2(__nv_bfloat16 lo, __nv_bfloat16 hi) {
    return (unsigned)__bfloat16_as_ushort(lo) |
           ((unsigned)__bfloat16_as_ushort(hi) << 16);
}

__device__ __forceinline__ void split3(float v, __nv_bfloat16& a0,
                                       __nv_bfloat16& a1, __nv_bfloat16& a2) {
    a0 = __float2bfloat16_rn(v);
    float r = v - __bfloat162float(a0);
    a1 = __float2bfloat16_rn(r);
    float r2 = r - __bfloat162float(a1);
    a2 = __float2bfloat16_rn(r2);
}

// ---------------------------------------------------------------------------
// Kernel 0: split embed into bf16x2 + squared norms. One warp per code.
// ---------------------------------------------------------------------------
__global__ void esplit_kernel(const float* __restrict__ embed) {
    int k    = blockIdx.x * 8 + (threadIdx.x >> 5);
    int lane = threadIdx.x & 31;
    const float4* e = (const float4*)(embed + (size_t)k * DC_);
    float s = 0.f;
    #pragma unroll
    for (int seg = lane; seg < DC_ / 4; seg += 32) {
        float4 v = e[seg];
        s += v.x * v.x + v.y * v.y + v.z * v.z + v.w * v.w;
        __nv_bfloat16 x0, x1, x2, y0, y1, y2, z0, z1, z2, w0, w1, w2;
        split3(v.x, x0, x1, x2); split3(v.y, y0, y1, y2);
        split3(v.z, z0, z1, z2); split3(v.w, w0, w1, w2);
        size_t o = (size_t)k * DC_ + seg * 4;
        *(uint2*)&g_e0[o] = make_uint2(pack2(x0, y0), pack2(z0, w0));
        *(uint2*)&g_e1[o] = make_uint2(pack2(x1, y1), pack2(z1, w1));
    }
    #pragma unroll
    for (int off = 16; off; off >>= 1) s += __shfl_xor_sync(0xFFFFFFFFu, s, off);
    if (lane == 0) g_en[k] = s;
}

__global__ void zero_cnt_kernel() { g_unc_cnt = 0; }

// ---------------------------------------------------------------------------
// Shared SIMT compute macro (encode/decode)
// ---------------------------------------------------------------------------
#define COMPUTE_TILE(AIDX, BIDX)                                              \
    _Pragma("unroll")                                                         \
    for (int kk = 0; kk < BK; kk++) {                                         \
        float4 a0 = *(float4*)&As[kk][(AIDX) * 8];                            \
        float4 a1 = *(float4*)&As[kk][(AIDX) * 8 + 4];                        \
        float4 q0 = *(float4*)&Bs[kk][(BIDX) * 8];                            \
        float4 q1 = *(float4*)&Bs[kk][(BIDX) * 8 + 4];                        \
        float av[8] = {a0.x,a0.y,a0.z,a0.w,a1.x,a1.y,a1.z,a1.w};              \
        float bw[8] = {q0.x,q0.y,q0.z,q0.w,q1.x,q1.y,q1.z,q1.w};              \
        _Pragma("unroll")                                                     \
        for (int i = 0; i < 8; i++)                                           \
            _Pragma("unroll")                                                 \
            for (int j = 0; j < 8; j++) c[i][j] += av[i] * bw[j];             \
    }

// ---------------------------------------------------------------------------
// Kernel 1: encode GEMM, epilogue splits h into bf16x3.
// ---------------------------------------------------------------------------
__global__ __launch_bounds__(256, 2)
void encode_kernel(const float* __restrict__ x,
                   const float* __restrict__ W_in,
                   const float* __restrict__ b_in) {
    __shared__ float As[BK][BM];
    __shared__ float Bs[BK][BN];
    int tid = threadIdx.x;
    int tx = tid & 15, ty = tid >> 4;
    int m0 = blockIdx.x * BM;
    int n0 = blockIdx.y * BN;
    int b  = m0 / T_;
    int t0 = m0 % T_;
    const float* xb = x + (size_t)b * H_ * T_ + t0;

    int a_kk = tid >> 5, a_mm = (tid & 31) * 4;
    int b_rr = tid >> 1, b_k4 = (tid & 1) * 4;

    float c[8][8];
    #pragma unroll
    for (int i = 0; i < 8; i++)
        #pragma unroll
        for (int j = 0; j < 8; j++) c[i][j] = 0.f;

    float4 ra = *(const float4*)&xb[(size_t)a_kk * T_ + a_mm];
    float4 rb = *(const float4*)&W_in[(size_t)(n0 + b_rr) * H_ + b_k4];

    for (int k0 = 0; k0 < H_; k0 += BK) {
        *(float4*)&As[a_kk][a_mm] = ra;
        Bs[b_k4 + 0][b_rr] = rb.x;
        Bs[b_k4 + 1][b_rr] = rb.y;
        Bs[b_k4 + 2][b_rr] = rb.z;
        Bs[b_k4 + 3][b_rr] = rb.w;
        __syncthreads();
        if (k0 + BK < H_) {
            ra = *(const float4*)&xb[(size_t)(k0 + BK + a_kk) * T_ + a_mm];
            rb = *(const float4*)&W_in[(size_t)(n0 + b_rr) * H_ + k0 + BK + b_k4];
        }
        COMPUTE_TILE(ty, tx)
        __syncthreads();
    }

    float bj[8];
    #pragma unroll
    for (int j = 0; j < 8; j++) bj[j] = b_in[n0 + tx * 8 + j];
    #pragma unroll
    for (int i = 0; i < 8; i++) {
        size_t row = (size_t)(m0 + ty * 8 + i) * DC_ + n0 + tx * 8;
        uint4 p0, p1, p2;
        unsigned* u0 = (unsigned*)&p0;
        unsigned* u1 = (unsigned*)&p1;
        unsigned* u2 = (unsigned*)&p2;
        #pragma unroll
        for (int jp = 0; jp < 4; jp++) {
            float va = c[i][2 * jp]     + bj[2 * jp];
            float vb = c[i][2 * jp + 1] + bj[2 * jp + 1];
            __nv_bfloat16 a0, a1, a2, q0, q1, q2;
            split3(va, a0, a1, a2);
            split3(vb, q0, q1, q2);
            u0[jp] = pack2(a0, q0);
            u1[jp] = pack2(a1, q1);
            u2[jp] = pack2(a2, q2);
        }
        *(uint4*)&g_h0[row] = p0;
        *(uint4*)&g_h1[row] = p1;
        *(uint4*)&g_h2[row] = p2;
    }
}

// ---------------------------------------------------------------------------
// Kernel 2: fused score GEMM + top-2 argmax, cp.async 3-stage pipeline.
//   Stage = {A0,A1,B0,B1} 128x32 bf16 tiles. 1024 flattened (kc,d0) steps.
// ---------------------------------------------------------------------------
__global__ __launch_bounds__(256, 2)
void argmax_mma_kernel() {
    extern __shared__ unsigned char smraw[];
    unsigned char* sm = (unsigned char*)(((uintptr_t)smraw + 1023) & ~(uintptr_t)1023);
    uint32_t smb = smem_u32(sm);
    __shared__ float MS[MM];
    __shared__ int   MI[MM];
    __shared__ float M2[MM];

    int tid  = threadIdx.x;
    int warp = tid >> 5, lane = tid & 31;
    int half = warp >> 2;                 // 0: codes 0-63, 1: codes 64-127
    int warpM = (warp & 3) * 32;
    int warpN = half * 64;
    int m0   = blockIdx.x * MM;

    const __nv_bfloat16* A0 = g_h0 + (size_t)m0 * DC_;
    const __nv_bfloat16* A1 = g_h1 + (size_t)m0 * DC_;

    // loader indexing: 2 x 16B segs per tile per thread
    int ld_row = tid >> 2;                // 0..63 (+64 on second seg)
    int ld_c   = tid & 3;                 // 16B column within 64B row
    unsigned ld_off0 = (unsigned)ld_row * 64 + ld_c * 16;
    unsigned ld_off1 = (unsigned)(ld_row + 64) * 64 + ld_c * 16;
    unsigned ld_sw0 = ld_off0 ^ ((ld_off0 >> 3) & 0x70);
    unsigned ld_sw1 = ld_off1 ^ ((ld_off1 >> 3) & 0x70);

    // ldmatrix lane address components
    int rA_lo = (lane & 7) + ((lane >> 3) & 1) * 8;   // A x4: row within 16
    int kA    = lane >> 4;                            // A x4: k-chunk select
    int rB_lo = lane & 7;                             // B x4: code within 8
    int kB    = (lane >> 3) & 1;                      // B x4: k-chunk select
    int nB    = (lane >> 4) & 1;                      // B x4: which nt of pair

    float best[2][2], sec[2][2];
    int   bidx[2][2];
    #pragma unroll
    for (int mt = 0; mt < 2; mt++)
        #pragma unroll
        for (int r = 0; r < 2; r++) {
            best[mt][r] = -3.4e38f; sec[mt][r] = -3.4e38f; bidx[mt][r] = 0;
        }

    float acc[2][8][4];
    #pragma unroll
    for (int mt = 0; mt < 2; mt++)
        #pragma unroll
        for (int nt = 0; nt < 8; nt++)
            #pragma unroll
            for (int q = 0; q < 4; q++) acc[mt][nt][q] = 0.f;

    // ---- stage issue: global step sg -> buffer buf ----
    auto issue = [&](int sg, int buf) {
        if (sg < TOT_STEPS) {
            int kc = (sg >> 4) * NN;
            int d0 = (sg & 15) * DKT;
            uint32_t sb = smb + buf * STAGE_B;
            const __nv_bfloat16* srcs[4] = {
                A0 + d0, A1 + d0,
                g_e0 + (size_t)kc * DC_ + d0, g_e1 + (size_t)kc * DC_ + d0};
            #pragma unroll
            for (int ti = 0; ti < 4; ti++) {
                const __nv_bfloat16* s = srcs[ti];
                cp16(sb + ti * TILE_B + ld_sw0,
                     s + (size_t)ld_row * DC_ + ld_c * 8);
                cp16(sb + ti * TILE_B + ld_sw1,
                     s + (size_t)(ld_row + 64) * DC_ + ld_c * 8);
            }
        }
        CP_COMMIT();
    };

    issue(0, 0);
    issue(1, 1);

    int buf = 0;
    for (int sg = 0; sg < TOT_STEPS; sg++) {
        CP_WAIT1();
        __syncthreads();
        int nbuf = buf + 2; if (nbuf >= NSTAGE) nbuf -= NSTAGE;
        issue(sg + 2, nbuf);

        uint32_t sb = smb + buf * STAGE_B;
        // ---- compute: 2 k16 steps over the 32-d stage ----
        #pragma unroll
        for (int k16 = 0; k16 < 2; k16++) {
            uint32_t Af[2][2][4];
            #pragma unroll
            for (int mt = 0; mt < 2; mt++) {
                int rowA = warpM + mt * 16 + rA_lo;
                unsigned off = (unsigned)rowA * 64 + (unsigned)(k16 * 2 + kA) * 16;
                unsigned sw  = off ^ ((off >> 3) & 0x70);
                ldsm_x4(Af[mt][0], sb + 0 * TILE_B + sw);
                ldsm_x4(Af[mt][1], sb + 1 * TILE_B + sw);
            }
            #pragma unroll
            for (int ntp = 0; ntp < 4; ntp++) {
                int rowB = warpN + (ntp * 2 + nB) * 8 + rB_lo;
                unsigned off = (unsigned)rowB * 64 + (unsigned)(k16 * 2 + kB) * 16;
                unsigned sw  = off ^ ((off >> 3) & 0x70);
                uint32_t Bf[2][4];
                ldsm_x4(Bf[0], sb + 2 * TILE_B + sw);
                ldsm_x4(Bf[1], sb + 3 * TILE_B + sw);
                #pragma unroll
                for (int mt = 0; mt < 2; mt++)
                    #pragma unroll
                    for (int h2 = 0; h2 < 2; h2++) {
                        float* a = acc[mt][ntp * 2 + h2];
                        mma16816(a, Af[mt][0], Bf[0] + h2 * 2);
                        mma16816(a, Af[mt][0], Bf[1] + h2 * 2);
                        mma16816(a, Af[mt][1], Bf[0] + h2 * 2);
                    }
            }
        }
        buf = buf + 1; if (buf >= NSTAGE) buf = 0;

        // ---- end of a 128-code chunk: top-2 update, then reset acc ----
        if ((sg & 15) == 15) {
            int kc = (sg >> 4) * NN;
            #pragma unroll
            for (int mt = 0; mt < 2; mt++)
                #pragma unroll
                for (int r = 0; r < 2; r++) {
                    float b1 = best[mt][r], b2 = sec[mt][r];
                    int   i1 = bidx[mt][r];
                    #pragma unroll
                    for (int nt = 0; nt < 8; nt++) {
                        #pragma unroll
                        for (int q = 0; q < 2; q++) {
                            int ncol = warpN + nt * 8 + (lane & 3) * 2 + q;
                            float s = 2.f * acc[mt][nt][r * 2 + q] - g_en[kc + ncol];
                            if (s > b1) { b2 = b1; b1 = s; i1 = kc + ncol; }
                            else if (s > b2) b2 = s;
                        }
                    }
                    best[mt][r] = b1; sec[mt][r] = b2; bidx[mt][r] = i1;
                }
            #pragma unroll
            for (int mt = 0; mt < 2; mt++)
                #pragma unroll
                for (int nt = 0; nt < 8; nt++)
                    #pragma unroll
                    for (int q = 0; q < 4; q++) acc[mt][nt][q] = 0.f;
        }
    }

    // ---- reduce across the 4 lanes sharing each row ----
    #pragma unroll
    for (int mt = 0; mt < 2; mt++)
        #pragma unroll
        for (int r = 0; r < 2; r++) {
            float b1 = best[mt][r], b2 = sec[mt][r];
            int   i1 = bidx[mt][r];
            #pragma unroll
            for (int off = 1; off <= 2; off <<= 1) {
                float c1 = __shfl_xor_sync(0xFFFFFFFFu, b1, off);
                int   ci = __shfl_xor_sync(0xFFFFFFFFu, i1, off);
                float c2 = __shfl_xor_sync(0xFFFFFFFFu, b2, off);
                if (c1 > b1) { b2 = fmaxf(b1, c2); b1 = c1; i1 = ci; }
                else { b2 = fmaxf(b2, c1); if (c1 == b1 && ci < i1) i1 = ci; }
            }
            best[mt][r] = b1; sec[mt][r] = b2; bidx[mt][r] = i1;
        }

    // ---- merge warp halves (codes 0-63 vs 64-127) ----
    __syncthreads();
    if (half == 1 && (lane & 3) == 0) {
        #pragma unroll
        for (int mt = 0; mt < 2; mt++)
            #pragma unroll
            for (int r = 0; r < 2; r++) {
                int row = warpM + mt * 16 + r * 8 + (lane >> 2);
                MS[row] = best[mt][r];
                MI[row] = bidx[mt][r];
                M2[row] = sec[mt][r];
            }
    }
    __syncthreads();
    if (half == 0 && (lane & 3) == 0) {
        #pragma unroll
        for (int mt = 0; mt < 2; mt++)
            #pragma unroll
            for (int r = 0; r < 2; r++) {
                int row = warpM + mt * 16 + r * 8 + (lane >> 2);
                float b1 = best[mt][r], b2 = sec[mt][r];
                int   i1 = bidx[mt][r];
                float c1 = MS[row], c2 = M2[row];
                int   ci = MI[row];
                if (c1 > b1) { b2 = fmaxf(b1, c2); b1 = c1; i1 = ci; }
                else { b2 = fmaxf(b2, c1); if (c1 == b1 && ci < i1) i1 = ci; }
                g_ind[m0 + row] = i1;
                if (b1 - b2 < DELTA) {
                    int p = atomicAdd(&g_unc_cnt, 1);
                    g_unc[p] = m0 + row;
                }
            }
    }
}

// ---------------------------------------------------------------------------
// Kernel 2b: exact fp32 rescoring fallback for uncertain tokens.
// ---------------------------------------------------------------------------
__global__ __launch_bounds__(256, 4)
void fallback_kernel(const float* __restrict__ embed) {
    __shared__ float hs[DC_];
    __shared__ float ws[8];
    __shared__ int   wi[8];
    int tid = threadIdx.x;
    int warp = tid >> 5, lane = tid & 31;
    int cnt = g_unc_cnt;

    for (int u = blockIdx.x; u < cnt; u += gridDim.x) {
        int tok = g_unc[u];
        __syncthreads();
        for (int d = tid; d < DC_; d += 256) {
            size_t o = (size_t)tok * DC_ + d;
            hs[d] = __bfloat162float(g_h0[o]) + __bfloat162float(g_h1[o]) +
                    __bfloat162float(g_h2[o]);
        }
        __syncthreads();

        float b1 = -3.4e38f;
        int   i1 = 0x7fffffff;
        for (int k = warp; k < K_; k += 8) {
            const float4* e = (const float4*)(embed + (size_t)k * DC_);
            float dot = 0.f;
            #pragma unroll
            for (int seg = lane; seg < DC_ / 4; seg += 32) {
                float4 v = e[seg];
                const float4 hv = *(const float4*)&hs[seg * 4];
                dot += v.x * hv.x + v.y * hv.y + v.z * hv.z + v.w * hv.w;
            }
            #pragma unroll
            for (int off = 16; off; off >>= 1)
                dot += __shfl_xor_sync(0xFFFFFFFFu, dot, off);
            float s = 2.f * dot - g_en[k];
            if (s > b1) { b1 = s; i1 = k; }   // k ascending per warp
        }
        if (lane == 0) { ws[warp] = b1; wi[warp] = i1; }
        __syncthreads();
        if (tid == 0) {
            float fb = ws[0]; int fi = wi[0];
            #pragma unroll
            for (int w = 1; w < 8; w++) {
                if (ws[w] > fb || (ws[w] == fb && wi[w] < fi)) {
                    fb = ws[w]; fi = wi[w];
                }
            }
            g_ind[tok] = fi;
        }
    }
}

// ---------------------------------------------------------------------------
// Kernel 3: decode GEMM with codebook gather + transposed coalesced write.
// ---------------------------------------------------------------------------
__global__ __launch_bounds__(256, 2)
void decode_kernel(const float* __restrict__ embed,
                   const float* __restrict__ W_out,
                   const float* __restrict__ b_out,
                   float* __restrict__ out) {
    __shared__ float As[BK][BM];
    __shared__ float Bs[BK][BN];
    __shared__ int   sind[BM];
    int tid = threadIdx.x;
    int tx = tid & 15, ty = tid >> 4;
    int m0 = blockIdx.x * BM;
    int n0 = blockIdx.y * BN;
    int b  = m0 / T_;
    int t0 = m0 % T_;

    if (tid < BM) sind[tid] = g_ind[m0 + tid];
    __syncthreads();

    int rr = tid >> 1, k4 = (tid & 1) * 4;
    const float* Abase = &embed[(size_t)sind[rr] * DC_ + k4];
    const float* Bbase = &W_out[(size_t)(n0 + rr) * DC_ + k4];

    float c[8][8];
    #pragma unroll
    for (int i = 0; i < 8; i++)
        #pragma unroll
        for (int j = 0; j < 8; j++) c[i][j] = 0.f;

    float4 ra = *(const float4*)Abase;
    float4 rb = *(const float4*)Bbase;

    for (int d0 = 0; d0 < DC_; d0 += BK) {
        As[k4 + 0][rr] = ra.x;
        As[k4 + 1][rr] = ra.y;
        As[k4 + 2][rr] = ra.z;
        As[k4 + 3][rr] = ra.w;
        Bs[k4 + 0][rr] = rb.x;
        Bs[k4 + 1][rr] = rb.y;
        Bs[k4 + 2][rr] = rb.z;
        Bs[k4 + 3][rr] = rb.w;
        __syncthreads();
        if (d0 + BK < DC_) {
            ra = *(const float4*)(Abase + d0 + BK);
            rb = *(const float4*)(Bbase + d0 + BK);
        }
        COMPUTE_TILE(tx, ty)
        __syncthreads();
    }

    float* ob = out + (size_t)b * H_ * T_ + t0 + tx * 8;
    #pragma unroll
    for (int j = 0; j < 8; j++) {
        int   n  = n0 + ty * 8 + j;
        float bb = b_out[n];
        *(float4*)&ob[(size_t)n * T_]     = make_float4(c[0][j]+bb, c[1][j]+bb, c[2][j]+bb, c[3][j]+bb);
        *(float4*)&ob[(size_t)n * T_ + 4] = make_float4(c[4][j]+bb, c[5][j]+bb, c[6][j]+bb, c[7][j]+bb);
    }
}

// ---------------------------------------------------------------------------
extern "C" void kernel_launch(void* const* d_in, const int* in_sizes, int n_in,
                              void* d_out, int out_size) {
    const float* x     = (const float*)d_in[0];
    const float* embed = (const float*)d_in[1];
    const float* W_in  = (const float*)d_in[2];
    const float* b_in  = (const float*)d_in[3];
    const float* W_out = (const float*)d_in[4];
    const float* b_out = (const float*)d_in[5];
    float* out = (float*)d_out;

    cudaFuncSetAttribute(argmax_mma_kernel,
                         cudaFuncAttributeMaxDynamicSharedMemorySize, SMEM_DYN);

    zero_cnt_kernel<<<1, 1>>>();
    esplit_kernel<<<K_ / 8, 256>>>(embed);
    encode_kernel<<<dim3(BT_ / BM, DC_ / BN), 256>>>(x, W_in, b_in);
    argmax_mma_kernel<<<BT_ / MM, 256, SMEM_DYN>>>();
    fallback_kernel<<<256, 256>>>(embed);
    decode_kernel<<<dim3(BT_ / BM, H_ / BN), 256>>>(embed, W_out, b_out, out);
}

// round 12
// speedup vs baseline: 5.1035x; 1.1165x over previous
#include <cuda_runtime.h>
#include <cuda_bf16.h>
#include <cstdint>

#define B_   8
#define H_   1024
#define T_   4096
#define DC_  512
#define K_   8192
#define BT_  (B_ * T_)

#define BM 128
#define BN 128
#define BK 8

// ---- HMMA pipeline tiling (argmax + decode) ----
#define MM   128                   // tokens per CTA
#define NN   128                   // codes / h-cols per chunk
#define DKT  32                    // d-columns per pipeline stage
#define TILE_B   (128 * DKT * 2)   // one 128x32 bf16 tile = 8 KB
#define STAGE_B  (4 * TILE_B)      // A0,A1,B0,B1 per stage = 32 KB
#define NSTAGE   3
#define SMEM_DYN (NSTAGE * STAGE_B + 1024)
#define TOT_STEPS ((K_ / NN) * (DC_ / DKT))   // 64 * 16 = 1024

#define DELTA 0.125f               // certainty margin for 2-split scores

// Scratch (static __device__ arrays per allocation rules)
__device__ __nv_bfloat16 g_h0[(size_t)BT_ * DC_];
__device__ __nv_bfloat16 g_h1[(size_t)BT_ * DC_];
__device__ __nv_bfloat16 g_h2[(size_t)BT_ * DC_];
__device__ __nv_bfloat16 g_e0[(size_t)K_ * DC_];
__device__ __nv_bfloat16 g_e1[(size_t)K_ * DC_];
__device__ __nv_bfloat16 g_w0[(size_t)H_ * DC_];
__device__ __nv_bfloat16 g_w1[(size_t)H_ * DC_];
__device__ float g_en[K_];
__device__ int   g_ind[BT_];
__device__ int   g_unc[BT_];
__device__ int   g_unc_cnt;

// ---------------------------------------------------------------------------
// helpers
// ---------------------------------------------------------------------------
__device__ __forceinline__ uint32_t smem_u32(const void* p) {
    uint32_t a;
    asm("{ .reg .u64 t; cvta.to.shared.u64 t, %1; cvt.u32.u64 %0, t; }"
        : "=r"(a) : "l"(p));
    return a;
}

__device__ __forceinline__ void cp16(uint32_t smem, const void* g) {
    asm volatile("cp.async.cg.shared.global [%0], [%1], 16;"
                 :: "r"(smem), "l"(g));
}
#define CP_COMMIT() asm volatile("cp.async.commit_group;" ::: "memory")
#define CP_WAIT1()  asm volatile("cp.async.wait_group 1;" ::: "memory")
#define CP_WAIT0()  asm volatile("cp.async.wait_group 0;" ::: "memory")

__device__ __forceinline__ void ldsm_x4(uint32_t* r, uint32_t addr) {
    asm volatile("ldmatrix.sync.aligned.m8n8.x4.shared.b16 {%0,%1,%2,%3}, [%4];"
                 : "=r"(r[0]), "=r"(r[1]), "=r"(r[2]), "=r"(r[3]) : "r"(addr));
}
__device__ __forceinline__ void mma16816(float* c, const uint32_t* a,
                                         const uint32_t* b) {
    asm volatile(
        "mma.sync.aligned.m16n8k16.row.col.f32.bf16.bf16.f32 "
        "{%0,%1,%2,%3}, {%4,%5,%6,%7}, {%8,%9}, {%0,%1,%2,%3};"
        : "+f"(c[0]), "+f"(c[1]), "+f"(c[2]), "+f"(c[3])
        : "r"(a[0]), "r"(a[1]), "r"(a[2]), "r"(a[3]), "r"(b[0]), "r"(b[1]));
}

__device__ __forceinline__ unsigned pack2(__nv_bfloat16 lo, __nv_bfloat16 hi) {
    return (unsigned)__bfloat16_as_ushort(lo) |
           ((unsigned)__bfloat16_as_ushort(hi) << 16);
}

__device__ __forceinline__ void split3(float v, __nv_bfloat16& a0,
                                       __nv_bfloat16& a1, __nv_bfloat16& a2) {
    a0 = __float2bfloat16_rn(v);
    float r = v - __bfloat162float(a0);
    a1 = __float2bfloat16_rn(r);
    float r2 = r - __bfloat162float(a1);
    a2 = __float2bfloat16_rn(r2);
}

// ---------------------------------------------------------------------------
// Kernel 0: split embed into bf16x2 + squared norms. One warp per code.
// ---------------------------------------------------------------------------
__global__ void esplit_kernel(const float* __restrict__ embed) {
    int k    = blockIdx.x * 8 + (threadIdx.x >> 5);
    int lane = threadIdx.x & 31;
    const float4* e = (const float4*)(embed + (size_t)k * DC_);
    float s = 0.f;
    #pragma unroll
    for (int seg = lane; seg < DC_ / 4; seg += 32) {
        float4 v = e[seg];
        s += v.x * v.x + v.y * v.y + v.z * v.z + v.w * v.w;
        __nv_bfloat16 x0, x1, x2, y0, y1, y2, z0, z1, z2, w0, w1, w2;
        split3(v.x, x0, x1, x2); split3(v.y, y0, y1, y2);
        split3(v.z, z0, z1, z2); split3(v.w, w0, w1, w2);
        size_t o = (size_t)k * DC_ + seg * 4;
        *(uint2*)&g_e0[o] = make_uint2(pack2(x0, y0), pack2(z0, w0));
        *(uint2*)&g_e1[o] = make_uint2(pack2(x1, y1), pack2(z1, w1));
    }
    #pragma unroll
    for (int off = 16; off; off >>= 1) s += __shfl_xor_sync(0xFFFFFFFFu, s, off);
    if (lane == 0) g_en[k] = s;
}

// Kernel 0b: split W_out into bf16x2.
__global__ void wsplit_kernel(const float* __restrict__ W_out) {
    int idx = (blockIdx.x * 256 + threadIdx.x) * 4;
    float4 v = *(const float4*)&W_out[idx];
    __nv_bfloat16 x0, x1, x2, y0, y1, y2, z0, z1, z2, w0, w1, w2;
    split3(v.x, x0, x1, x2); split3(v.y, y0, y1, y2);
    split3(v.z, z0, z1, z2); split3(v.w, w0, w1, w2);
    *(uint2*)&g_w0[idx] = make_uint2(pack2(x0, y0), pack2(z0, w0));
    *(uint2*)&g_w1[idx] = make_uint2(pack2(x1, y1), pack2(z1, w1));
}

__global__ void zero_cnt_kernel() { g_unc_cnt = 0; }

// ---------------------------------------------------------------------------
// Shared SIMT compute macro (encode)
// ---------------------------------------------------------------------------
#define COMPUTE_TILE(AIDX, BIDX)                                              \
    _Pragma("unroll")                                                         \
    for (int kk = 0; kk < BK; kk++) {                                         \
        float4 a0 = *(float4*)&As[kk][(AIDX) * 8];                            \
        float4 a1 = *(float4*)&As[kk][(AIDX) * 8 + 4];                        \
        float4 q0 = *(float4*)&Bs[kk][(BIDX) * 8];                            \
        float4 q1 = *(float4*)&Bs[kk][(BIDX) * 8 + 4];                        \
        float av[8] = {a0.x,a0.y,a0.z,a0.w,a1.x,a1.y,a1.z,a1.w};              \
        float bw[8] = {q0.x,q0.y,q0.z,q0.w,q1.x,q1.y,q1.z,q1.w};              \
        _Pragma("unroll")                                                     \
        for (int i = 0; i < 8; i++)                                           \
            _Pragma("unroll")                                                 \
            for (int j = 0; j < 8; j++) c[i][j] += av[i] * bw[j];             \
    }

// ---------------------------------------------------------------------------
// Kernel 1: encode GEMM (fp32 FFMA — feeds argmax decisions, must stay exact),
//   epilogue splits h into bf16x3.
// ---------------------------------------------------------------------------
__global__ __launch_bounds__(256, 2)
void encode_kernel(const float* __restrict__ x,
                   const float* __restrict__ W_in,
                   const float* __restrict__ b_in) {
    __shared__ float As[BK][BM];
    __shared__ float Bs[BK][BN];
    int tid = threadIdx.x;
    int tx = tid & 15, ty = tid >> 4;
    int m0 = blockIdx.x * BM;
    int n0 = blockIdx.y * BN;
    int b  = m0 / T_;
    int t0 = m0 % T_;
    const float* xb = x + (size_t)b * H_ * T_ + t0;

    int a_kk = tid >> 5, a_mm = (tid & 31) * 4;
    int b_rr = tid >> 1, b_k4 = (tid & 1) * 4;

    float c[8][8];
    #pragma unroll
    for (int i = 0; i < 8; i++)
        #pragma unroll
        for (int j = 0; j < 8; j++) c[i][j] = 0.f;

    float4 ra = *(const float4*)&xb[(size_t)a_kk * T_ + a_mm];
    float4 rb = *(const float4*)&W_in[(size_t)(n0 + b_rr) * H_ + b_k4];

    for (int k0 = 0; k0 < H_; k0 += BK) {
        *(float4*)&As[a_kk][a_mm] = ra;
        Bs[b_k4 + 0][b_rr] = rb.x;
        Bs[b_k4 + 1][b_rr] = rb.y;
        Bs[b_k4 + 2][b_rr] = rb.z;
        Bs[b_k4 + 3][b_rr] = rb.w;
        __syncthreads();
        if (k0 + BK < H_) {
            ra = *(const float4*)&xb[(size_t)(k0 + BK + a_kk) * T_ + a_mm];
            rb = *(const float4*)&W_in[(size_t)(n0 + b_rr) * H_ + k0 + BK + b_k4];
        }
        COMPUTE_TILE(ty, tx)
        __syncthreads();
    }

    float bj[8];
    #pragma unroll
    for (int j = 0; j < 8; j++) bj[j] = b_in[n0 + tx * 8 + j];
    #pragma unroll
    for (int i = 0; i < 8; i++) {
        size_t row = (size_t)(m0 + ty * 8 + i) * DC_ + n0 + tx * 8;
        uint4 p0, p1, p2;
        unsigned* u0 = (unsigned*)&p0;
        unsigned* u1 = (unsigned*)&p1;
        unsigned* u2 = (unsigned*)&p2;
        #pragma unroll
        for (int jp = 0; jp < 4; jp++) {
            float va = c[i][2 * jp]     + bj[2 * jp];
            float vb = c[i][2 * jp + 1] + bj[2 * jp + 1];
            __nv_bfloat16 a0, a1, a2, q0, q1, q2;
            split3(va, a0, a1, a2);
            split3(vb, q0, q1, q2);
            u0[jp] = pack2(a0, q0);
            u1[jp] = pack2(a1, q1);
            u2[jp] = pack2(a2, q2);
        }
        *(uint4*)&g_h0[row] = p0;
        *(uint4*)&g_h1[row] = p1;
        *(uint4*)&g_h2[row] = p2;
    }
}

// ---------------------------------------------------------------------------
// Kernel 2: fused score GEMM + top-2 argmax, cp.async 3-stage pipeline.
// ---------------------------------------------------------------------------
__global__ __launch_bounds__(256, 2)
void argmax_mma_kernel() {
    extern __shared__ unsigned char smraw[];
    unsigned char* sm = (unsigned char*)(((uintptr_t)smraw + 1023) & ~(uintptr_t)1023);
    uint32_t smb = smem_u32(sm);
    __shared__ float MS[MM];
    __shared__ int   MI[MM];
    __shared__ float M2[MM];

    int tid  = threadIdx.x;
    int warp = tid >> 5, lane = tid & 31;
    int half = warp >> 2;                 // 0: codes 0-63, 1: codes 64-127
    int warpM = (warp & 3) * 32;
    int warpN = half * 64;
    int m0   = blockIdx.x * MM;

    const __nv_bfloat16* A0 = g_h0 + (size_t)m0 * DC_;
    const __nv_bfloat16* A1 = g_h1 + (size_t)m0 * DC_;

    // loader indexing: 2 x 16B segs per tile per thread
    int ld_row = tid >> 2;
    int ld_c   = tid & 3;
    unsigned ld_off0 = (unsigned)ld_row * 64 + ld_c * 16;
    unsigned ld_off1 = (unsigned)(ld_row + 64) * 64 + ld_c * 16;
    unsigned ld_sw0 = ld_off0 ^ ((ld_off0 >> 3) & 0x70);
    unsigned ld_sw1 = ld_off1 ^ ((ld_off1 >> 3) & 0x70);

    // ldmatrix lane address components
    int rA_lo = (lane & 7) + ((lane >> 3) & 1) * 8;
    int kA    = lane >> 4;
    int rB_lo = lane & 7;
    int kB    = (lane >> 3) & 1;
    int nB    = (lane >> 4) & 1;

    float best[2][2], sec[2][2];
    int   bidx[2][2];
    #pragma unroll
    for (int mt = 0; mt < 2; mt++)
        #pragma unroll
        for (int r = 0; r < 2; r++) {
            best[mt][r] = -3.4e38f; sec[mt][r] = -3.4e38f; bidx[mt][r] = 0;
        }

    float acc[2][8][4];
    #pragma unroll
    for (int mt = 0; mt < 2; mt++)
        #pragma unroll
        for (int nt = 0; nt < 8; nt++)
            #pragma unroll
            for (int q = 0; q < 4; q++) acc[mt][nt][q] = 0.f;

    auto issue = [&](int sg, int buf) {
        if (sg < TOT_STEPS) {
            int kc = (sg >> 4) * NN;
            int d0 = (sg & 15) * DKT;
            uint32_t sb = smb + buf * STAGE_B;
            const __nv_bfloat16* srcs[4] = {
                A0 + d0, A1 + d0,
                g_e0 + (size_t)kc * DC_ + d0, g_e1 + (size_t)kc * DC_ + d0};
            #pragma unroll
            for (int ti = 0; ti < 4; ti++) {
                const __nv_bfloat16* s = srcs[ti];
                cp16(sb + ti * TILE_B + ld_sw0,
                     s + (size_t)ld_row * DC_ + ld_c * 8);
                cp16(sb + ti * TILE_B + ld_sw1,
                     s + (size_t)(ld_row + 64) * DC_ + ld_c * 8);
            }
        }
        CP_COMMIT();
    };

    issue(0, 0);
    issue(1, 1);

    int buf = 0;
    for (int sg = 0; sg < TOT_STEPS; sg++) {
        CP_WAIT1();
        __syncthreads();
        int nbuf = buf + 2; if (nbuf >= NSTAGE) nbuf -= NSTAGE;
        issue(sg + 2, nbuf);

        uint32_t sb = smb + buf * STAGE_B;
        #pragma unroll
        for (int k16 = 0; k16 < 2; k16++) {
            uint32_t Af[2][2][4];
            #pragma unroll
            for (int mt = 0; mt < 2; mt++) {
                int rowA = warpM + mt * 16 + rA_lo;
                unsigned off = (unsigned)rowA * 64 + (unsigned)(k16 * 2 + kA) * 16;
                unsigned sw  = off ^ ((off >> 3) & 0x70);
                ldsm_x4(Af[mt][0], sb + 0 * TILE_B + sw);
                ldsm_x4(Af[mt][1], sb + 1 * TILE_B + sw);
            }
            #pragma unroll
            for (int ntp = 0; ntp < 4; ntp++) {
                int rowB = warpN + (ntp * 2 + nB) * 8 + rB_lo;
                unsigned off = (unsigned)rowB * 64 + (unsigned)(k16 * 2 + kB) * 16;
                unsigned sw  = off ^ ((off >> 3) & 0x70);
                uint32_t Bf[2][4];
                ldsm_x4(Bf[0], sb + 2 * TILE_B + sw);
                ldsm_x4(Bf[1], sb + 3 * TILE_B + sw);
                #pragma unroll
                for (int mt = 0; mt < 2; mt++)
                    #pragma unroll
                    for (int h2 = 0; h2 < 2; h2++) {
                        float* a = acc[mt][ntp * 2 + h2];
                        mma16816(a, Af[mt][0], Bf[0] + h2 * 2);
                        mma16816(a, Af[mt][0], Bf[1] + h2 * 2);
                        mma16816(a, Af[mt][1], Bf[0] + h2 * 2);
                    }
            }
        }
        buf = buf + 1; if (buf >= NSTAGE) buf = 0;

        if ((sg & 15) == 15) {
            int kc = (sg >> 4) * NN;
            #pragma unroll
            for (int mt = 0; mt < 2; mt++)
                #pragma unroll
                for (int r = 0; r < 2; r++) {
                    float b1 = best[mt][r], b2 = sec[mt][r];
                    int   i1 = bidx[mt][r];
                    #pragma unroll
                    for (int nt = 0; nt < 8; nt++) {
                        #pragma unroll
                        for (int q = 0; q < 2; q++) {
                            int ncol = warpN + nt * 8 + (lane & 3) * 2 + q;
                            float s = 2.f * acc[mt][nt][r * 2 + q] - g_en[kc + ncol];
                            if (s > b1) { b2 = b1; b1 = s; i1 = kc + ncol; }
                            else if (s > b2) b2 = s;
                        }
                    }
                    best[mt][r] = b1; sec[mt][r] = b2; bidx[mt][r] = i1;
                }
            #pragma unroll
            for (int mt = 0; mt < 2; mt++)
                #pragma unroll
                for (int nt = 0; nt < 8; nt++)
                    #pragma unroll
                    for (int q = 0; q < 4; q++) acc[mt][nt][q] = 0.f;
        }
    }

    #pragma unroll
    for (int mt = 0; mt < 2; mt++)
        #pragma unroll
        for (int r = 0; r < 2; r++) {
            float b1 = best[mt][r], b2 = sec[mt][r];
            int   i1 = bidx[mt][r];
            #pragma unroll
            for (int off = 1; off <= 2; off <<= 1) {
                float c1 = __shfl_xor_sync(0xFFFFFFFFu, b1, off);
                int   ci = __shfl_xor_sync(0xFFFFFFFFu, i1, off);
                float c2 = __shfl_xor_sync(0xFFFFFFFFu, b2, off);
                if (c1 > b1) { b2 = fmaxf(b1, c2); b1 = c1; i1 = ci; }
                else { b2 = fmaxf(b2, c1); if (c1 == b1 && ci < i1) i1 = ci; }
            }
            best[mt][r] = b1; sec[mt][r] = b2; bidx[mt][r] = i1;
        }

    __syncthreads();
    if (half == 1 && (lane & 3) == 0) {
        #pragma unroll
        for (int mt = 0; mt < 2; mt++)
            #pragma unroll
            for (int r = 0; r < 2; r++) {
                int row = warpM + mt * 16 + r * 8 + (lane >> 2);
                MS[row] = best[mt][r];
                MI[row] = bidx[mt][r];
                M2[row] = sec[mt][r];
            }
    }
    __syncthreads();
    if (half == 0 && (lane & 3) == 0) {
        #pragma unroll
        for (int mt = 0; mt < 2; mt++)
            #pragma unroll
            for (int r = 0; r < 2; r++) {
                int row = warpM + mt * 16 + r * 8 + (lane >> 2);
                float b1 = best[mt][r], b2 = sec[mt][r];
                int   i1 = bidx[mt][r];
                float c1 = MS[row], c2 = M2[row];
                int   ci = MI[row];
                if (c1 > b1) { b2 = fmaxf(b1, c2); b1 = c1; i1 = ci; }
                else { b2 = fmaxf(b2, c1); if (c1 == b1 && ci < i1) i1 = ci; }
                g_ind[m0 + row] = i1;
                if (b1 - b2 < DELTA) {
                    int p = atomicAdd(&g_unc_cnt, 1);
                    g_unc[p] = m0 + row;
                }
            }
    }
}

// ---------------------------------------------------------------------------
// Kernel 2b: exact fp32 rescoring fallback for uncertain tokens.
// ---------------------------------------------------------------------------
__global__ __launch_bounds__(256, 4)
void fallback_kernel(const float* __restrict__ embed) {
    __shared__ float hs[DC_];
    __shared__ float ws[8];
    __shared__ int   wi[8];
    int tid = threadIdx.x;
    int warp = tid >> 5, lane = tid & 31;
    int cnt = g_unc_cnt;

    for (int u = blockIdx.x; u < cnt; u += gridDim.x) {
        int tok = g_unc[u];
        __syncthreads();
        for (int d = tid; d < DC_; d += 256) {
            size_t o = (size_t)tok * DC_ + d;
            hs[d] = __bfloat162float(g_h0[o]) + __bfloat162float(g_h1[o]) +
                    __bfloat162float(g_h2[o]);
        }
        __syncthreads();

        float b1 = -3.4e38f;
        int   i1 = 0x7fffffff;
        for (int k = warp; k < K_; k += 8) {
            const float4* e = (const float4*)(embed + (size_t)k * DC_);
            float dot = 0.f;
            #pragma unroll
            for (int seg = lane; seg < DC_ / 4; seg += 32) {
                float4 v = e[seg];
                const float4 hv = *(const float4*)&hs[seg * 4];
                dot += v.x * hv.x + v.y * hv.y + v.z * hv.z + v.w * hv.w;
            }
            #pragma unroll
            for (int off = 16; off; off >>= 1)
                dot += __shfl_xor_sync(0xFFFFFFFFu, dot, off);
            float s = 2.f * dot - g_en[k];
            if (s > b1) { b1 = s; i1 = k; }
        }
        if (lane == 0) { ws[warp] = b1; wi[warp] = i1; }
        __syncthreads();
        if (tid == 0) {
            float fb = ws[0]; int fi = wi[0];
            #pragma unroll
            for (int w = 1; w < 8; w++) {
                if (ws[w] > fb || (ws[w] == fb && wi[w] < fi)) {
                    fb = ws[w]; fi = wi[w];
                }
            }
            g_ind[tok] = fi;
        }
    }
}

// ---------------------------------------------------------------------------
// Kernel 3: decode GEMM on HMMA (bf16x2, 3 products) with gathered quantize.
//   A = g_e0/g_e1 rows gathered by g_ind, B = g_w0/g_w1 (W_out splits).
//   Same cp.async 3-stage pipeline; epilogue stages through smem (stride-129)
//   for conflict-free transposed coalesced writes to out[b, n, t].
// ---------------------------------------------------------------------------
__global__ __launch_bounds__(256, 2)
void decode_mma_kernel(const float* __restrict__ b_out,
                       float* __restrict__ out) {
    extern __shared__ unsigned char smraw[];
    unsigned char* sm = (unsigned char*)(((uintptr_t)smraw + 1023) & ~(uintptr_t)1023);
    uint32_t smb = smem_u32(sm);
    float* smf = (float*)sm;               // epilogue staging (reuses pipeline)

    int tid  = threadIdx.x;
    int warp = tid >> 5, lane = tid & 31;
    int warpM = (warp & 3) * 32;
    int warpN = (warp >> 2) * 64;
    int m0 = blockIdx.x * MM;
    int n0 = blockIdx.y * NN;
    int b  = m0 / T_;
    int t0 = m0 % T_;

    // loader indexing (identical to argmax)
    int ld_row = tid >> 2;
    int ld_c   = tid & 3;
    unsigned ld_off0 = (unsigned)ld_row * 64 + ld_c * 16;
    unsigned ld_off1 = (unsigned)(ld_row + 64) * 64 + ld_c * 16;
    unsigned ld_sw0 = ld_off0 ^ ((ld_off0 >> 3) & 0x70);
    unsigned ld_sw1 = ld_off1 ^ ((ld_off1 >> 3) & 0x70);

    // gather indices for this loader thread's two A rows
    size_t si0 = (size_t)g_ind[m0 + ld_row] * DC_;
    size_t si1 = (size_t)g_ind[m0 + ld_row + 64] * DC_;
    size_t wr0 = (size_t)(n0 + ld_row) * DC_;
    size_t wr1 = (size_t)(n0 + ld_row + 64) * DC_;

    int rA_lo = (lane & 7) + ((lane >> 3) & 1) * 8;
    int kA    = lane >> 4;
    int rB_lo = lane & 7;
    int kB    = (lane >> 3) & 1;
    int nB    = (lane >> 4) & 1;

    float acc[2][8][4];
    #pragma unroll
    for (int mt = 0; mt < 2; mt++)
        #pragma unroll
        for (int nt = 0; nt < 8; nt++)
            #pragma unroll
            for (int q = 0; q < 4; q++) acc[mt][nt][q] = 0.f;

    auto issue = [&](int sg, int buf) {
        if (sg < DC_ / DKT) {
            int d0 = sg * DKT;
            uint32_t sb = smb + buf * STAGE_B;
            int dc = d0 + ld_c * 8;
            cp16(sb + 0 * TILE_B + ld_sw0, g_e0 + si0 + dc);
            cp16(sb + 0 * TILE_B + ld_sw1, g_e0 + si1 + dc);
            cp16(sb + 1 * TILE_B + ld_sw0, g_e1 + si0 + dc);
            cp16(sb + 1 * TILE_B + ld_sw1, g_e1 + si1 + dc);
            cp16(sb + 2 * TILE_B + ld_sw0, g_w0 + wr0 + dc);
            cp16(sb + 2 * TILE_B + ld_sw1, g_w0 + wr1 + dc);
            cp16(sb + 3 * TILE_B + ld_sw0, g_w1 + wr0 + dc);
            cp16(sb + 3 * TILE_B + ld_sw1, g_w1 + wr1 + dc);
        }
        CP_COMMIT();
    };

    issue(0, 0);
    issue(1, 1);

    int buf = 0;
    for (int sg = 0; sg < DC_ / DKT; sg++) {
        CP_WAIT1();
        __syncthreads();
        int nbuf = buf + 2; if (nbuf >= NSTAGE) nbuf -= NSTAGE;
        issue(sg + 2, nbuf);

        uint32_t sb = smb + buf * STAGE_B;
        #pragma unroll
        for (int k16 = 0; k16 < 2; k16++) {
            uint32_t Af[2][2][4];
            #pragma unroll
            for (int mt = 0; mt < 2; mt++) {
                int rowA = warpM + mt * 16 + rA_lo;
                unsigned off = (unsigned)rowA * 64 + (unsigned)(k16 * 2 + kA) * 16;
                unsigned sw  = off ^ ((off >> 3) & 0x70);
                ldsm_x4(Af[mt][0], sb + 0 * TILE_B + sw);
                ldsm_x4(Af[mt][1], sb + 1 * TILE_B + sw);
            }
            #pragma unroll
            for (int ntp = 0; ntp < 4; ntp++) {
                int rowB = warpN + (ntp * 2 + nB) * 8 + rB_lo;
                unsigned off = (unsigned)rowB * 64 + (unsigned)(k16 * 2 + kB) * 16;
                unsigned sw  = off ^ ((off >> 3) & 0x70);
                uint32_t Bf[2][4];
                ldsm_x4(Bf[0], sb + 2 * TILE_B + sw);
                ldsm_x4(Bf[1], sb + 3 * TILE_B + sw);
                #pragma unroll
                for (int mt = 0; mt < 2; mt++)
                    #pragma unroll
                    for (int h2 = 0; h2 < 2; h2++) {
                        float* a = acc[mt][ntp * 2 + h2];
                        mma16816(a, Af[mt][0], Bf[0] + h2 * 2);
                        mma16816(a, Af[mt][0], Bf[1] + h2 * 2);
                        mma16816(a, Af[mt][1], Bf[0] + h2 * 2);
                    }
            }
        }
        buf = buf + 1; if (buf >= NSTAGE) buf = 0;
    }

    // ---- epilogue: stage 128x128 result through smem (stride 129) ----
    CP_WAIT0();
    __syncthreads();
    #pragma unroll
    for (int mt = 0; mt < 2; mt++)
        #pragma unroll
        for (int nt = 0; nt < 8; nt++) {
            int row = warpM + mt * 16 + (lane >> 2);
            int col = warpN + nt * 8 + (lane & 3) * 2;
            smf[row * 129 + col]           = acc[mt][nt][0];
            smf[row * 129 + col + 1]       = acc[mt][nt][1];
            smf[(row + 8) * 129 + col]     = acc[mt][nt][2];
            smf[(row + 8) * 129 + col + 1] = acc[mt][nt][3];
        }
    __syncthreads();

    float* ob = out + (size_t)b * H_ * T_ + t0;
    #pragma unroll
    for (int rep = 0; rep < 64; rep++) {
        int idx = rep * 256 + tid;
        int n = idx >> 7;        // 0..127
        int t = idx & 127;       // 0..127, tid-consecutive -> coalesced
        ob[(size_t)(n0 + n) * T_ + t] = smf[t * 129 + n] + b_out[n0 + n];
    }
}

// ---------------------------------------------------------------------------
extern "C" void kernel_launch(void* const* d_in, const int* in_sizes, int n_in,
                              void* d_out, int out_size) {
    const float* x     = (const float*)d_in[0];
    const float* embed = (const float*)d_in[1];
    const float* W_in  = (const float*)d_in[2];
    const float* b_in  = (const float*)d_in[3];
    const float* W_out = (const float*)d_in[4];
    const float* b_out = (const float*)d_in[5];
    float* out = (float*)d_out;

    cudaFuncSetAttribute(argmax_mma_kernel,
                         cudaFuncAttributeMaxDynamicSharedMemorySize, SMEM_DYN);
    cudaFuncSetAttribute(decode_mma_kernel,
                         cudaFuncAttributeMaxDynamicSharedMemorySize, SMEM_DYN);

    zero_cnt_kernel<<<1, 1>>>();
    esplit_kernel<<<K_ / 8, 256>>>(embed);
    wsplit_kernel<<<(H_ * DC_) / 1024, 256>>>(W_out);
    encode_kernel<<<dim3(BT_ / BM, DC_ / BN), 256>>>(x, W_in, b_in);
    argmax_mma_kernel<<<BT_ / MM, 256, SMEM_DYN>>>();
    fallback_kernel<<<256, 256>>>(embed);
    decode_mma_kernel<<<dim3(BT_ / MM, H_ / NN), 256, SMEM_DYN>>>(b_out, out);
}